// round 7
// baseline (speedup 1.0000x reference)
#include <cuda_runtime.h>
#include <cuda_bf16.h>
#include <cstdint>
#include <cstddef>

// Problem constants
#define BATCH   16
#define NTOK    577
#define CDIM    768
#define HEADS   12
#define DHEAD   64
#define MROWS   (BATCH * NTOK)          // 9232
#define QKVCOLS (3 * CDIM)              // 2304
#define BHTOT   (BATCH * HEADS)         // 192

typedef unsigned long long ull;

// ---------------- packed f32x2 helpers (FFMA2 path) -------------------------
__device__ __forceinline__ ull dup2(float v) {
    ull r; unsigned u = __float_as_uint(v);
    asm("mov.b64 %0, {%1, %2};" : "=l"(r) : "r"(u), "r"(u));
    return r;
}
__device__ __forceinline__ void fma2(ull& d, ull a, ull b) {
    asm("fma.rn.f32x2 %0, %1, %2, %0;" : "+l"(d) : "l"(a), "l"(b));
}
__device__ __forceinline__ float2 unpack2(ull v) {
    unsigned lo, hi;
    asm("mov.b64 {%0, %1}, %2;" : "=r"(lo), "=r"(hi) : "l"(v));
    return make_float2(__uint_as_float(lo), __uint_as_float(hi));
}

// ---------------- scratch (no allocations allowed -> device globals) --------
__device__ float g_qkv[(size_t)MROWS * QKVCOLS];              // (B*N, 3C)
__device__ float g_Q[(size_t)BHTOT * NTOK * DHEAD];           // (B*H, N, D)
__device__ float g_K[(size_t)BHTOT * NTOK * DHEAD];
__device__ float g_V[(size_t)BHTOT * NTOK * DHEAD];
__device__ float g_attn[(size_t)MROWS * CDIM];                // (B*N, C)

// ======================= SGEMM (FFMA2): C = A@B + bias ======================
// BM=128, BN=128, BK=8, 256 threads, 8x8 microtile as 8x4 f32x2.
// A stored DUPLICATED-transposed in smem: Asd[k][2r]=Asd[k][2r+1]=A[r][k],
// so a 16B LDS yields two packed (a,a) f32x2 operands with zero pack MOVs.
// Double buffered; one __syncthreads per k-step.
template <int Nc, int Kc>
__device__ __forceinline__ void sgemm2_body(const float* __restrict__ A,
                                            const float* __restrict__ Bm,
                                            const float* __restrict__ bias,
                                            float* __restrict__ Cm, int M) {
    __shared__ float Asd[2][8][256];
    __shared__ float Bs[2][8][128];

    const int tid = threadIdx.x;
    const int block_row = blockIdx.y * 128;
    const int block_col = blockIdx.x * 128;
    const int tr = (tid >> 4) << 3;   // 0..120
    const int tc = (tid & 15) << 3;   // 0..120

    const int a_row = tid >> 1;
    const int a_col = (tid & 1) << 2;
    const int b_row = tid >> 5;
    const int b_col = (tid & 31) << 2;

    const float* Ag = A + (size_t)block_row * Kc;
    const float* Bg = Bm + block_col;

    ull acc[8][4];
#pragma unroll
    for (int i = 0; i < 8; i++)
#pragma unroll
        for (int j = 0; j < 4; j++) acc[i][j] = 0ull;

    // prologue: tile 0 -> buf 0
    {
        float4 av = make_float4(0.f, 0.f, 0.f, 0.f);
        if (block_row + a_row < M)
            av = *(const float4*)(Ag + (size_t)a_row * Kc + a_col);
        float4 bv = *(const float4*)(Bg + (size_t)b_row * Nc + b_col);
        float2 d0 = make_float2(av.x, av.x);
        float2 d1 = make_float2(av.y, av.y);
        float2 d2 = make_float2(av.z, av.z);
        float2 d3 = make_float2(av.w, av.w);
        *(float2*)&Asd[0][a_col + 0][2 * a_row] = d0;
        *(float2*)&Asd[0][a_col + 1][2 * a_row] = d1;
        *(float2*)&Asd[0][a_col + 2][2 * a_row] = d2;
        *(float2*)&Asd[0][a_col + 3][2 * a_row] = d3;
        *(float4*)&Bs[0][b_row][b_col] = bv;
    }
    __syncthreads();

    const int NKT = Kc / 8;
    int buf = 0;
    for (int kt = 0; kt < NKT; kt++) {
        const bool more = (kt + 1) < NKT;
        float4 av2 = make_float4(0.f, 0.f, 0.f, 0.f);
        float4 bv2;
        if (more) {
            int k0 = (kt + 1) * 8;
            if (block_row + a_row < M)
                av2 = *(const float4*)(Ag + (size_t)a_row * Kc + k0 + a_col);
            bv2 = *(const float4*)(Bg + (size_t)(k0 + b_row) * Nc + b_col);
        }

#pragma unroll
        for (int kk = 0; kk < 8; kk++) {
            ulonglong2 t0 = *(const ulonglong2*)&Asd[buf][kk][2 * tr];
            ulonglong2 t1 = *(const ulonglong2*)&Asd[buf][kk][2 * tr + 4];
            ulonglong2 t2 = *(const ulonglong2*)&Asd[buf][kk][2 * tr + 8];
            ulonglong2 t3 = *(const ulonglong2*)&Asd[buf][kk][2 * tr + 12];
            ulonglong2 u0 = *(const ulonglong2*)&Bs[buf][kk][tc];
            ulonglong2 u1 = *(const ulonglong2*)&Bs[buf][kk][tc + 4];
            ull a2[8] = {t0.x, t0.y, t1.x, t1.y, t2.x, t2.y, t3.x, t3.y};
            ull b2[4] = {u0.x, u0.y, u1.x, u1.y};
#pragma unroll
            for (int i = 0; i < 8; i++) {
                fma2(acc[i][0], a2[i], b2[0]);
                fma2(acc[i][1], a2[i], b2[1]);
                fma2(acc[i][2], a2[i], b2[2]);
                fma2(acc[i][3], a2[i], b2[3]);
            }
        }

        if (more) {
            int nb = buf ^ 1;
            float2 d0 = make_float2(av2.x, av2.x);
            float2 d1 = make_float2(av2.y, av2.y);
            float2 d2 = make_float2(av2.z, av2.z);
            float2 d3 = make_float2(av2.w, av2.w);
            *(float2*)&Asd[nb][a_col + 0][2 * a_row] = d0;
            *(float2*)&Asd[nb][a_col + 1][2 * a_row] = d1;
            *(float2*)&Asd[nb][a_col + 2][2 * a_row] = d2;
            *(float2*)&Asd[nb][a_col + 3][2 * a_row] = d3;
            *(float4*)&Bs[nb][b_row][b_col] = bv2;
            buf = nb;
            __syncthreads();
        }
    }

#pragma unroll
    for (int i = 0; i < 8; i++) {
        int r = block_row + tr + i;
        if (r < M) {
#pragma unroll
            for (int j = 0; j < 4; j++) {
                int c = block_col + tc + (j << 1);
                float2 p = unpack2(acc[i][j]);
                float2 ov;
                ov.x = p.x + bias[c + 0];
                ov.y = p.y + bias[c + 1];
                *(float2*)(Cm + (size_t)r * Nc + c) = ov;
            }
        }
    }
}

__global__ __launch_bounds__(256, 2) void k_gemm_qkv(const float* __restrict__ x,
                                                     const float* __restrict__ w,
                                                     const float* __restrict__ b) {
    sgemm2_body<QKVCOLS, CDIM>(x, w, b, g_qkv, MROWS);
}

__global__ __launch_bounds__(256, 2) void k_gemm_proj(const float* __restrict__ w,
                                                      const float* __restrict__ b,
                                                      float* __restrict__ out) {
    sgemm2_body<CDIM, CDIM>(g_attn, w, b, out, MROWS);
}

// =============== RoPE + split (B,N,3,H,D) -> Q/K/V (B*H, N, D) ==============
__global__ __launch_bounds__(256) void k_rope_split(const float* __restrict__ cosb,
                                                    const float* __restrict__ sinb) {
    int idx = blockIdx.x * blockDim.x + threadIdx.x;
    const int total = BATCH * HEADS * NTOK * (DHEAD / 2);
    if (idx >= total) return;

    int d2 = idx & 31;
    int n  = (idx >> 5) % NTOK;
    int h  = (idx / (32 * NTOK)) % HEADS;
    int b  = idx / (32 * NTOK * HEADS);

    size_t base = (size_t)(b * NTOK + n) * QKVCOLS + h * DHEAD + (d2 << 1);
    float2 q = *(const float2*)(g_qkv + base);
    float2 k = *(const float2*)(g_qkv + base + CDIM);
    float2 v = *(const float2*)(g_qkv + base + 2 * CDIM);

    if (n > 0) {
        float c = cosb[(size_t)(n - 1) * 32 + d2];
        float s = sinb[(size_t)(n - 1) * 32 + d2];
        float2 qr, kr;
        qr.x = q.x * c - q.y * s;  qr.y = q.x * s + q.y * c;
        kr.x = k.x * c - k.y * s;  kr.y = k.x * s + k.y * c;
        q = qr; k = kr;
    }

    size_t o = ((size_t)(b * HEADS + h) * NTOK + n) * DHEAD + (d2 << 1);
    *(float2*)(g_Q + o) = q;
    *(float2*)(g_K + o) = k;
    *(float2*)(g_V + o) = v;
}

// ====================== Flash attention, FFMA2, 64x64 tiles =================
// K^T tile swizzled at PAIR granularity so (k_c,k_{c+1}) is a contiguous 8B
// LDS (packed f32x2 B operand). Q/P scalars duplicated via mov.b64 packs
// (alu pipe, overlaps fma pipe). smem = 48KB static.
__global__ __launch_bounds__(256) void k_attn() {
    __shared__ float Qs[DHEAD][64];   // Qs[d][r]
    __shared__ float KP[64][64];      // K^T pair-swizzled, then P row-major
    __shared__ float Vs[64][DHEAD];   // Vs[c][d]

    const int tid = threadIdx.x;
    const int ty = tid >> 4;
    const int tx = tid & 15;
    const int bh = blockIdx.y;
    const int q0 = blockIdx.x * 64;

    const float* Qg = g_Q + (size_t)bh * NTOK * DHEAD;
    const float* Kg = g_K + (size_t)bh * NTOK * DHEAD;
    const float* Vg = g_V + (size_t)bh * NTOK * DHEAD;

    // load Q tile, transposed
#pragma unroll
    for (int it = 0; it < 4; it++) {
        int idx = tid + it * 256;
        int r  = idx >> 4;
        int d4 = (idx & 15) << 2;
        float4 v = make_float4(0.f, 0.f, 0.f, 0.f);
        if (q0 + r < NTOK) v = *(const float4*)(Qg + (size_t)(q0 + r) * DHEAD + d4);
        Qs[d4 + 0][r] = v.x;
        Qs[d4 + 1][r] = v.y;
        Qs[d4 + 2][r] = v.z;
        Qs[d4 + 3][r] = v.w;
    }

    float m_i[4], l_i[4];
    ull o2[4][2];
#pragma unroll
    for (int i = 0; i < 4; i++) {
        m_i[i] = -1e30f;
        l_i[i] = 0.f;
        o2[i][0] = 0ull;
        o2[i][1] = 0ull;
    }
    const float scale = 0.125f;  // D^-0.5, D=64

    for (int kt = 0; kt < 10; kt++) {
        const int k0 = kt * 64;

        __syncthreads();  // prior PV done; KP/Vs free (also orders Q stores)

        // load K (transposed + pair-granularity swizzle) and V (row-major)
#pragma unroll
        for (int it = 0; it < 4; it++) {
            int idx = tid + it * 256;
            int r  = idx >> 4;
            int d4 = (idx & 15) << 2;
            float4 kv = make_float4(0.f, 0.f, 0.f, 0.f);
            float4 vv = make_float4(0.f, 0.f, 0.f, 0.f);
            if (k0 + r < NTOK) {
                kv = *(const float4*)(Kg + (size_t)(k0 + r) * DHEAD + d4);
                vv = *(const float4*)(Vg + (size_t)(k0 + r) * DHEAD + d4);
            }
            const int pr = r >> 1, lo = r & 1;
            KP[d4 + 0][(((pr) ^ ((d4 + 0) & 31)) << 1) | lo] = kv.x;
            KP[d4 + 1][(((pr) ^ ((d4 + 1) & 31)) << 1) | lo] = kv.y;
            KP[d4 + 2][(((pr) ^ ((d4 + 2) & 31)) << 1) | lo] = kv.z;
            KP[d4 + 3][(((pr) ^ ((d4 + 3) & 31)) << 1) | lo] = kv.w;
            *(float4*)&Vs[r][d4] = vv;
        }
        __syncthreads();

        // S = Q @ K^T  (packed over key pairs)
        ull s2[4][2];
#pragma unroll
        for (int i = 0; i < 4; i++) { s2[i][0] = 0ull; s2[i][1] = 0ull; }

#pragma unroll
        for (int d = 0; d < 64; d++) {
            float4 a = *(const float4*)&Qs[d][ty << 2];
            const int sw = d & 31;
            ull b01 = *(const ull*)&KP[d][((2 * tx) ^ sw) << 1];
            ull b23 = *(const ull*)&KP[d][((2 * tx + 1) ^ sw) << 1];
            ull a0 = dup2(a.x), a1 = dup2(a.y), a2 = dup2(a.z), a3 = dup2(a.w);
            fma2(s2[0][0], a0, b01); fma2(s2[0][1], a0, b23);
            fma2(s2[1][0], a1, b01); fma2(s2[1][1], a1, b23);
            fma2(s2[2][0], a2, b01); fma2(s2[2][1], a2, b23);
            fma2(s2[3][0], a3, b01); fma2(s2[3][1], a3, b23);
        }

        // unpack + online softmax (per query row, reduce across 16 tx lanes)
        float s[4][4];
#pragma unroll
        for (int i = 0; i < 4; i++) {
            float2 u0 = unpack2(s2[i][0]);
            float2 u1 = unpack2(s2[i][1]);
            s[i][0] = u0.x; s[i][1] = u0.y; s[i][2] = u1.x; s[i][3] = u1.y;
        }

        float fi[4];
#pragma unroll
        for (int i = 0; i < 4; i++) {
            float rm = -1e30f;
#pragma unroll
            for (int j = 0; j < 4; j++) {
                float v = s[i][j] * scale;
                if (k0 + (tx << 2) + j >= NTOK) v = -1e30f;
                s[i][j] = v;
                rm = fmaxf(rm, v);
            }
#pragma unroll
            for (int off = 8; off >= 1; off >>= 1)
                rm = fmaxf(rm, __shfl_xor_sync(0xffffffffu, rm, off));
            float mn = fmaxf(m_i[i], rm);
            fi[i] = __expf(m_i[i] - mn);
            m_i[i] = mn;
            float rs = 0.f;
#pragma unroll
            for (int j = 0; j < 4; j++) {
                float p = __expf(s[i][j] - mn);
                s[i][j] = p;
                rs += p;
            }
#pragma unroll
            for (int off = 8; off >= 1; off >>= 1)
                rs += __shfl_xor_sync(0xffffffffu, rs, off);
            l_i[i] = l_i[i] * fi[i] + rs;
            ull f2 = dup2(fi[i]);
            // o *= fi  (packed: o = o*fi + 0)
            ull z = 0ull;
            ull t0 = z, t1 = z;
            fma2(t0, o2[i][0], f2);
            fma2(t1, o2[i][1], f2);
            o2[i][0] = t0;
            o2[i][1] = t1;
        }

        __syncthreads();  // all K reads done; KP becomes P buffer

#pragma unroll
        for (int i = 0; i < 4; i++)
#pragma unroll
            for (int j = 0; j < 4; j++)
                KP[(ty << 2) + i][(tx << 2) + j] = s[i][j];

        __syncthreads();  // P visible

        // O += P @ V  (packed over output dims)
#pragma unroll
        for (int c = 0; c < 64; c++) {
            ulonglong2 vq = *(const ulonglong2*)&Vs[c][tx << 2];
            ull p0 = dup2(KP[(ty << 2) + 0][c]);
            ull p1 = dup2(KP[(ty << 2) + 1][c]);
            ull p2 = dup2(KP[(ty << 2) + 2][c]);
            ull p3 = dup2(KP[(ty << 2) + 3][c]);
            fma2(o2[0][0], p0, vq.x); fma2(o2[0][1], p0, vq.y);
            fma2(o2[1][0], p1, vq.x); fma2(o2[1][1], p1, vq.y);
            fma2(o2[2][0], p2, vq.x); fma2(o2[2][1], p2, vq.y);
            fma2(o2[3][0], p3, vq.x); fma2(o2[3][1], p3, vq.y);
        }
    }

    // write (B, N, H*D) for the proj GEMM
    const int b = bh / HEADS;
    const int h = bh % HEADS;
#pragma unroll
    for (int i = 0; i < 4; i++) {
        int n = q0 + (ty << 2) + i;
        if (n < NTOK) {
            float inv = 1.f / l_i[i];
            float2 u0 = unpack2(o2[i][0]);
            float2 u1 = unpack2(o2[i][1]);
            float4 r;
            r.x = u0.x * inv;
            r.y = u0.y * inv;
            r.z = u1.x * inv;
            r.w = u1.y * inv;
            *(float4*)(g_attn + (size_t)(b * NTOK + n) * CDIM + h * DHEAD + (tx << 2)) = r;
        }
    }
}

// ================================ launch ====================================
extern "C" void kernel_launch(void* const* d_in, const int* in_sizes, int n_in,
                              void* d_out, int out_size) {
    const float* x      = (const float*)d_in[0];
    const float* cosb   = (const float*)d_in[1];
    const float* sinb   = (const float*)d_in[2];
    const float* w_qkv  = (const float*)d_in[3];
    const float* b_qkv  = (const float*)d_in[4];
    const float* w_proj = (const float*)d_in[5];
    const float* b_proj = (const float*)d_in[6];
    float* out = (float*)d_out;

    // 1) QKV GEMM
    {
        dim3 grid(QKVCOLS / 128, (MROWS + 127) / 128);
        k_gemm_qkv<<<grid, 256>>>(x, w_qkv, b_qkv);
    }
    // 2) RoPE + split/transpose
    {
        int total = BATCH * HEADS * NTOK * (DHEAD / 2);
        k_rope_split<<<(total + 255) / 256, 256>>>(cosb, sinb);
    }
    // 3) attention
    {
        dim3 grid((NTOK + 63) / 64, BHTOT);
        k_attn<<<grid, 256>>>();
    }
    // 4) output projection
    {
        dim3 grid(CDIM / 128, (MROWS + 127) / 128);
        k_gemm_proj<<<grid, 256>>>(w_proj, b_proj, out);
    }
}

// round 9
// speedup vs baseline: 1.5571x; 1.5571x over previous
#include <cuda_runtime.h>
#include <cuda_bf16.h>
#include <cstdint>
#include <cstddef>

// Problem constants
#define BATCH   16
#define NTOK    577
#define CDIM    768
#define HEADS   12
#define DHEAD   64
#define MROWS   (BATCH * NTOK)          // 9232
#define QKVCOLS (3 * CDIM)              // 2304
#define BHTOT   (BATCH * HEADS)         // 192

// ===================== helpers ==============================================
__device__ __forceinline__ uint32_t smem_to_u32(const void* smem_ptr) {
    uint32_t addr;
    asm("{ .reg .u64 tmp; cvta.to.shared.u64 tmp, %1; cvt.u32.u64 %0, tmp; }"
        : "=r"(addr) : "l"(smem_ptr));
    return addr;
}

__device__ __forceinline__ void ldsm4(uint32_t* r, uint32_t addr) {
    asm volatile("ldmatrix.sync.aligned.m8n8.x4.shared.b16 {%0,%1,%2,%3}, [%4];"
                 : "=r"(r[0]), "=r"(r[1]), "=r"(r[2]), "=r"(r[3]) : "r"(addr));
}

__device__ __forceinline__ void mma16816(float* c, const uint32_t* a,
                                         uint32_t b0, uint32_t b1) {
    asm volatile(
        "mma.sync.aligned.m16n8k16.row.col.f32.bf16.bf16.f32 "
        "{%0,%1,%2,%3}, {%4,%5,%6,%7}, {%8,%9}, {%0,%1,%2,%3};"
        : "+f"(c[0]), "+f"(c[1]), "+f"(c[2]), "+f"(c[3])
        : "r"(a[0]), "r"(a[1]), "r"(a[2]), "r"(a[3]), "r"(b0), "r"(b1));
}

// ---------------- scratch (no allocations allowed -> device globals) --------
__device__ float g_qkv[(size_t)MROWS * QKVCOLS];              // (B*N, 3C)
__device__ float g_Q[(size_t)BHTOT * NTOK * DHEAD];           // (B*H, N, D)
__device__ float g_K[(size_t)BHTOT * NTOK * DHEAD];
__device__ float g_V[(size_t)BHTOT * NTOK * DHEAD];
__device__ float g_attn[(size_t)MROWS * CDIM];                // (B*N, C)

// bf16 hi/lo split operands for tensor-core GEMMs
__device__ __nv_bfloat16 gAh[(size_t)MROWS * CDIM];           // x split
__device__ __nv_bfloat16 gAl[(size_t)MROWS * CDIM];
__device__ __nv_bfloat16 gCh[(size_t)MROWS * CDIM];           // attn-out split
__device__ __nv_bfloat16 gCl[(size_t)MROWS * CDIM];
__device__ __nv_bfloat16 gWqh[(size_t)QKVCOLS * CDIM];        // w_qkv^T split
__device__ __nv_bfloat16 gWql[(size_t)QKVCOLS * CDIM];
__device__ __nv_bfloat16 gWph[(size_t)CDIM * CDIM];           // w_proj^T split
__device__ __nv_bfloat16 gWpl[(size_t)CDIM * CDIM];

// ==================== fp32 -> bf16 hi/lo split (row-major) ==================
__global__ __launch_bounds__(256) void k_split4(const float* __restrict__ in,
                                                __nv_bfloat16* __restrict__ oh,
                                                __nv_bfloat16* __restrict__ ol,
                                                int n4) {
    int i = blockIdx.x * blockDim.x + threadIdx.x;
    if (i >= n4) return;
    float4 v = ((const float4*)in)[i];
    float f[4] = {v.x, v.y, v.z, v.w};
    __align__(8) __nv_bfloat16 h[4];
    __align__(8) __nv_bfloat16 l[4];
#pragma unroll
    for (int j = 0; j < 4; j++) {
        h[j] = __float2bfloat16_rn(f[j]);
        l[j] = __float2bfloat16_rn(f[j] - __bfloat162float(h[j]));
    }
    *(uint2*)(oh + 4 * (size_t)i) = *(uint2*)h;
    *(uint2*)(ol + 4 * (size_t)i) = *(uint2*)l;
}

// ============ W[K][N] -> Wt_hi/Wt_lo[N][K] bf16 (transpose + split) =========
__global__ __launch_bounds__(256) void k_wsplit_t(const float* __restrict__ w,
                                                  __nv_bfloat16* __restrict__ oh,
                                                  __nv_bfloat16* __restrict__ ol,
                                                  int K, int N) {
    __shared__ float t[32][33];
    int n0 = blockIdx.x * 32, k0 = blockIdx.y * 32;
    int tx = threadIdx.x, ty = threadIdx.y;
#pragma unroll
    for (int j = 0; j < 32; j += 8)
        t[ty + j][tx] = w[(size_t)(k0 + ty + j) * N + n0 + tx];
    __syncthreads();
#pragma unroll
    for (int j = 0; j < 32; j += 8) {
        float v = t[tx][ty + j];
        int n = n0 + ty + j, k = k0 + tx;
        __nv_bfloat16 h = __float2bfloat16_rn(v);
        __nv_bfloat16 l = __float2bfloat16_rn(v - __bfloat162float(h));
        oh[(size_t)n * K + k] = h;
        ol[(size_t)n * K + k] = l;
    }
}

// =================== HMMA bf16x3 GEMM: C = A@B + bias =======================
// A (M x 768) hi/lo bf16 row-major; B supplied TRANSPOSED (N x 768) hi/lo.
// Tile 128x128, BK=32, 8 warps (2x4), warp tile 64x32.
// D += Ah*Bh + Ah*Bl + Al*Bh  (bf16x3 split, ~1e-5 rel err)
// smem: 2 buffers x 4 tiles (Ah,Al,Bh,Bl) x 8KB = 64KB, double buffered.
// 16B-chunk swizzle: chunk c at row r -> c ^ ((r>>1)&3); conflict-free ldmatrix.
#define GT_TILE 8192                    // 128 x 32 bf16
#define GT_BUF  (4 * GT_TILE)           // 32KB / stage
#define GT_SMEM (2 * GT_BUF)            // 64KB

__global__ __launch_bounds__(256) void k_gemm_mma(
    const __nv_bfloat16* __restrict__ Ah, const __nv_bfloat16* __restrict__ Al,
    const __nv_bfloat16* __restrict__ Bh, const __nv_bfloat16* __restrict__ Bl,
    const float* __restrict__ bias, float* __restrict__ C, int M, int N) {
    extern __shared__ __align__(128) char smem[];
    const uint32_t sbase = smem_to_u32(smem);

    const int tid  = threadIdx.x;
    const int lane = tid & 31;
    const int wid  = tid >> 5;
    const int wm   = wid >> 2;          // 0..1 : M offset wm*64
    const int wn   = wid & 3;           // 0..3 : N offset wn*32
    const int block_row = blockIdx.y * 128;
    const int block_col = blockIdx.x * 128;

    // ---- global->smem chunk mapping (2 chunks per thread per tile) ----
    const int u0 = tid, u1 = tid + 256;
    const int r0 = u0 >> 2, c0 = u0 & 3;
    const int r1 = u1 >> 2, c1 = u1 & 3;
    const uint32_t so0 = (uint32_t)(r0 * 64 + ((c0 ^ ((r0 >> 1) & 3)) << 4));
    const uint32_t so1 = (uint32_t)(r1 * 64 + ((c1 ^ ((r1 >> 1) & 3)) << 4));
    const bool a0ok = (block_row + r0) < M;
    const bool a1ok = (block_row + r1) < M;
    const size_t gA0 = (size_t)(block_row + r0) * CDIM + c0 * 8;
    const size_t gA1 = (size_t)(block_row + r1) * CDIM + c1 * 8;
    const size_t gB0 = (size_t)(block_col + r0) * CDIM + c0 * 8;
    const size_t gB1 = (size_t)(block_col + r1) * CDIM + c1 * 8;

    // ---- ldmatrix source offsets (loop invariant) ----
    const int lrow = lane & 15;
    const int lkc  = lane >> 4;          // 0/1 -> k chunk within k16
    uint32_t offA[2][4], offB[2][2];
#pragma unroll
    for (int kk2 = 0; kk2 < 2; kk2++) {
        int cc = kk2 * 2 + lkc;          // logical 16B chunk (k / 8)
#pragma unroll
        for (int mi = 0; mi < 4; mi++) {
            int rr = wm * 64 + mi * 16 + lrow;
            offA[kk2][mi] = (uint32_t)(rr * 64 + ((cc ^ ((rr >> 1) & 3)) << 4));
        }
#pragma unroll
        for (int nb = 0; nb < 2; nb++) {
            int rr = wn * 32 + nb * 16 + lrow;
            offB[kk2][nb] = (uint32_t)(rr * 64 + ((cc ^ ((rr >> 1) & 3)) << 4));
        }
    }

    float acc[4][4][4];
#pragma unroll
    for (int mi = 0; mi < 4; mi++)
#pragma unroll
        for (int ni = 0; ni < 4; ni++)
#pragma unroll
            for (int j = 0; j < 4; j++) acc[mi][ni][j] = 0.f;

    const int NSTAGE = CDIM / 32;        // 24

    // ---- prologue: stage 0 -> buf 0 ----
    {
        char* b = smem;
        uint4 z = make_uint4(0, 0, 0, 0);
        *(uint4*)(b + so0)               = a0ok ? *(const uint4*)(Ah + gA0) : z;
        *(uint4*)(b + so1)               = a1ok ? *(const uint4*)(Ah + gA1) : z;
        *(uint4*)(b + GT_TILE + so0)     = a0ok ? *(const uint4*)(Al + gA0) : z;
        *(uint4*)(b + GT_TILE + so1)     = a1ok ? *(const uint4*)(Al + gA1) : z;
        *(uint4*)(b + 2 * GT_TILE + so0) = *(const uint4*)(Bh + gB0);
        *(uint4*)(b + 2 * GT_TILE + so1) = *(const uint4*)(Bh + gB1);
        *(uint4*)(b + 3 * GT_TILE + so0) = *(const uint4*)(Bl + gB0);
        *(uint4*)(b + 3 * GT_TILE + so1) = *(const uint4*)(Bl + gB1);
    }
    __syncthreads();

    for (int s = 0; s < NSTAGE; s++) {
        const int bsel = s & 1;
        const uint32_t tbase = sbase + bsel * GT_BUF;

        // prefetch next stage to regs (overlaps MMA block below)
        uint4 p[8];
        const bool more = (s + 1) < NSTAGE;
        if (more) {
            const int ko = (s + 1) * 32;
            uint4 z = make_uint4(0, 0, 0, 0);
            p[0] = a0ok ? *(const uint4*)(Ah + gA0 + ko) : z;
            p[1] = a0ok ? *(const uint4*)(Al + gA0 + ko) : z;
            p[2] = *(const uint4*)(Bh + gB0 + ko);
            p[3] = *(const uint4*)(Bl + gB0 + ko);
            p[4] = a1ok ? *(const uint4*)(Ah + gA1 + ko) : z;
            p[5] = a1ok ? *(const uint4*)(Al + gA1 + ko) : z;
            p[6] = *(const uint4*)(Bh + gB1 + ko);
            p[7] = *(const uint4*)(Bl + gB1 + ko);
        }

        // ---- compute on buffer bsel ----
#pragma unroll
        for (int kk2 = 0; kk2 < 2; kk2++) {
            uint32_t ah[4][4], al[4][4], bh[2][4], bl[2][4];
#pragma unroll
            for (int mi = 0; mi < 4; mi++) {
                ldsm4(ah[mi], tbase + offA[kk2][mi]);
                ldsm4(al[mi], tbase + GT_TILE + offA[kk2][mi]);
            }
#pragma unroll
            for (int nb = 0; nb < 2; nb++) {
                ldsm4(bh[nb], tbase + 2 * GT_TILE + offB[kk2][nb]);
                ldsm4(bl[nb], tbase + 3 * GT_TILE + offB[kk2][nb]);
            }
#pragma unroll
            for (int mi = 0; mi < 4; mi++) {
#pragma unroll
                for (int ni = 0; ni < 4; ni++) {
                    const int nb = ni >> 1;
                    const int nsub = ni & 1;   // regs (0,2) or (1,3)
                    uint32_t bh0 = bh[nb][nsub], bh1 = bh[nb][nsub + 2];
                    uint32_t bl0 = bl[nb][nsub], bl1 = bl[nb][nsub + 2];
                    mma16816(acc[mi][ni], ah[mi], bh0, bh1);
                    mma16816(acc[mi][ni], ah[mi], bl0, bl1);
                    mma16816(acc[mi][ni], al[mi], bh0, bh1);
                }
            }
        }

        if (more) {
            __syncthreads();   // everyone done reading buf bsel^1 (stage s-1)
            char* b = smem + (bsel ^ 1) * GT_BUF;
            *(uint4*)(b + so0)               = p[0];
            *(uint4*)(b + GT_TILE + so0)     = p[1];
            *(uint4*)(b + 2 * GT_TILE + so0) = p[2];
            *(uint4*)(b + 3 * GT_TILE + so0) = p[3];
            *(uint4*)(b + so1)               = p[4];
            *(uint4*)(b + GT_TILE + so1)     = p[5];
            *(uint4*)(b + 2 * GT_TILE + so1) = p[6];
            *(uint4*)(b + 3 * GT_TILE + so1) = p[7];
            __syncthreads();   // next buffer visible
        }
    }

    // ---- epilogue: acc frag layout -> global + bias ----
    const int erow = lane >> 2;
    const int ecol = (lane & 3) << 1;
#pragma unroll
    for (int mi = 0; mi < 4; mi++) {
#pragma unroll
        for (int ni = 0; ni < 4; ni++) {
            int r = block_row + wm * 64 + mi * 16 + erow;
            int col = block_col + wn * 32 + ni * 8 + ecol;
            float2 bv = *(const float2*)(bias + col);
            if (r < M) {
                float2 o = make_float2(acc[mi][ni][0] + bv.x,
                                       acc[mi][ni][1] + bv.y);
                *(float2*)(C + (size_t)r * N + col) = o;
            }
            if (r + 8 < M) {
                float2 o = make_float2(acc[mi][ni][2] + bv.x,
                                       acc[mi][ni][3] + bv.y);
                *(float2*)(C + (size_t)(r + 8) * N + col) = o;
            }
        }
    }
}

// =============== RoPE + split (B,N,3,H,D) -> Q/K/V (B*H, N, D) ==============
__global__ __launch_bounds__(256) void k_rope_split(const float* __restrict__ cosb,
                                                    const float* __restrict__ sinb) {
    int idx = blockIdx.x * blockDim.x + threadIdx.x;
    const int total = BATCH * HEADS * NTOK * (DHEAD / 2);
    if (idx >= total) return;

    int d2 = idx & 31;
    int n  = (idx >> 5) % NTOK;
    int h  = (idx / (32 * NTOK)) % HEADS;
    int b  = idx / (32 * NTOK * HEADS);

    size_t base = (size_t)(b * NTOK + n) * QKVCOLS + h * DHEAD + (d2 << 1);
    float2 q = *(const float2*)(g_qkv + base);
    float2 k = *(const float2*)(g_qkv + base + CDIM);
    float2 v = *(const float2*)(g_qkv + base + 2 * CDIM);

    if (n > 0) {
        float c = cosb[(size_t)(n - 1) * 32 + d2];
        float s = sinb[(size_t)(n - 1) * 32 + d2];
        float2 qr, kr;
        qr.x = q.x * c - q.y * s;  qr.y = q.x * s + q.y * c;
        kr.x = k.x * c - k.y * s;  kr.y = k.x * s + k.y * c;
        q = qr; k = kr;
    }

    size_t o = ((size_t)(b * HEADS + h) * NTOK + n) * DHEAD + (d2 << 1);
    *(float2*)(g_Q + o) = q;
    *(float2*)(g_K + o) = k;
    *(float2*)(g_V + o) = v;
}

// ====================== Flash attention, fp32, 64x64 tiles ==================
__global__ __launch_bounds__(256) void k_attn() {
    __shared__ float Qs[DHEAD][64];   // Qs[d][r]
    __shared__ float KP[64][64];      // Ks[d][c^swz] then Ps[r][c]
    __shared__ float Vs[64][DHEAD];   // Vs[c][d]

    const int tid = threadIdx.x;
    const int ty = tid >> 4;
    const int tx = tid & 15;
    const int bh = blockIdx.y;
    const int q0 = blockIdx.x * 64;

    const float* Qg = g_Q + (size_t)bh * NTOK * DHEAD;
    const float* Kg = g_K + (size_t)bh * NTOK * DHEAD;
    const float* Vg = g_V + (size_t)bh * NTOK * DHEAD;

#pragma unroll
    for (int it = 0; it < 4; it++) {
        int idx = tid + it * 256;
        int r  = idx >> 4;
        int d4 = (idx & 15) << 2;
        float4 v = make_float4(0.f, 0.f, 0.f, 0.f);
        if (q0 + r < NTOK) v = *(const float4*)(Qg + (size_t)(q0 + r) * DHEAD + d4);
        Qs[d4 + 0][r] = v.x;
        Qs[d4 + 1][r] = v.y;
        Qs[d4 + 2][r] = v.z;
        Qs[d4 + 3][r] = v.w;
    }

    float m_i[4], l_i[4], o[4][4];
#pragma unroll
    for (int i = 0; i < 4; i++) {
        m_i[i] = -1e30f;
        l_i[i] = 0.f;
#pragma unroll
        for (int j = 0; j < 4; j++) o[i][j] = 0.f;
    }
    const float scale = 0.125f;

    for (int kt = 0; kt < 10; kt++) {
        const int k0 = kt * 64;

        __syncthreads();

#pragma unroll
        for (int it = 0; it < 4; it++) {
            int idx = tid + it * 256;
            int r  = idx >> 4;
            int d4 = (idx & 15) << 2;
            float4 kv = make_float4(0.f, 0.f, 0.f, 0.f);
            float4 vv = make_float4(0.f, 0.f, 0.f, 0.f);
            if (k0 + r < NTOK) {
                kv = *(const float4*)(Kg + (size_t)(k0 + r) * DHEAD + d4);
                vv = *(const float4*)(Vg + (size_t)(k0 + r) * DHEAD + d4);
            }
            KP[d4 + 0][r ^ ((d4 + 0) & 31)] = kv.x;
            KP[d4 + 1][r ^ ((d4 + 1) & 31)] = kv.y;
            KP[d4 + 2][r ^ ((d4 + 2) & 31)] = kv.z;
            KP[d4 + 3][r ^ ((d4 + 3) & 31)] = kv.w;
            *(float4*)&Vs[r][d4] = vv;
        }
        __syncthreads();

        float s[4][4];
#pragma unroll
        for (int i = 0; i < 4; i++)
#pragma unroll
            for (int j = 0; j < 4; j++) s[i][j] = 0.f;

#pragma unroll
        for (int d = 0; d < 64; d++) {
            float4 a = *(const float4*)&Qs[d][ty << 2];
            const int sw = d & 31;
            float b0 = KP[d][((tx << 2) + 0) ^ sw];
            float b1 = KP[d][((tx << 2) + 1) ^ sw];
            float b2 = KP[d][((tx << 2) + 2) ^ sw];
            float b3 = KP[d][((tx << 2) + 3) ^ sw];
            s[0][0] = fmaf(a.x, b0, s[0][0]); s[0][1] = fmaf(a.x, b1, s[0][1]);
            s[0][2] = fmaf(a.x, b2, s[0][2]); s[0][3] = fmaf(a.x, b3, s[0][3]);
            s[1][0] = fmaf(a.y, b0, s[1][0]); s[1][1] = fmaf(a.y, b1, s[1][1]);
            s[1][2] = fmaf(a.y, b2, s[1][2]); s[1][3] = fmaf(a.y, b3, s[1][3]);
            s[2][0] = fmaf(a.z, b0, s[2][0]); s[2][1] = fmaf(a.z, b1, s[2][1]);
            s[2][2] = fmaf(a.z, b2, s[2][2]); s[2][3] = fmaf(a.z, b3, s[2][3]);
            s[3][0] = fmaf(a.w, b0, s[3][0]); s[3][1] = fmaf(a.w, b1, s[3][1]);
            s[3][2] = fmaf(a.w, b2, s[3][2]); s[3][3] = fmaf(a.w, b3, s[3][3]);
        }

#pragma unroll
        for (int i = 0; i < 4; i++) {
            float rm = -1e30f;
#pragma unroll
            for (int j = 0; j < 4; j++) {
                float v = s[i][j] * scale;
                if (k0 + (tx << 2) + j >= NTOK) v = -1e30f;
                s[i][j] = v;
                rm = fmaxf(rm, v);
            }
#pragma unroll
            for (int off = 8; off >= 1; off >>= 1)
                rm = fmaxf(rm, __shfl_xor_sync(0xffffffffu, rm, off));
            float mn = fmaxf(m_i[i], rm);
            float fi = __expf(m_i[i] - mn);
            m_i[i] = mn;
            float rs = 0.f;
#pragma unroll
            for (int j = 0; j < 4; j++) {
                float p = __expf(s[i][j] - mn);
                s[i][j] = p;
                rs += p;
            }
#pragma unroll
            for (int off = 8; off >= 1; off >>= 1)
                rs += __shfl_xor_sync(0xffffffffu, rs, off);
            l_i[i] = l_i[i] * fi + rs;
#pragma unroll
            for (int j = 0; j < 4; j++) o[i][j] *= fi;
        }

        __syncthreads();

#pragma unroll
        for (int i = 0; i < 4; i++)
#pragma unroll
            for (int j = 0; j < 4; j++)
                KP[(ty << 2) + i][(tx << 2) + j] = s[i][j];

        __syncthreads();

#pragma unroll
        for (int c = 0; c < 64; c++) {
            float4 vv = *(const float4*)&Vs[c][tx << 2];
            float p0 = KP[(ty << 2) + 0][c];
            float p1 = KP[(ty << 2) + 1][c];
            float p2 = KP[(ty << 2) + 2][c];
            float p3 = KP[(ty << 2) + 3][c];
            o[0][0] = fmaf(p0, vv.x, o[0][0]); o[0][1] = fmaf(p0, vv.y, o[0][1]);
            o[0][2] = fmaf(p0, vv.z, o[0][2]); o[0][3] = fmaf(p0, vv.w, o[0][3]);
            o[1][0] = fmaf(p1, vv.x, o[1][0]); o[1][1] = fmaf(p1, vv.y, o[1][1]);
            o[1][2] = fmaf(p1, vv.z, o[1][2]); o[1][3] = fmaf(p1, vv.w, o[1][3]);
            o[2][0] = fmaf(p2, vv.x, o[2][0]); o[2][1] = fmaf(p2, vv.y, o[2][1]);
            o[2][2] = fmaf(p2, vv.z, o[2][2]); o[2][3] = fmaf(p2, vv.w, o[2][3]);
            o[3][0] = fmaf(p3, vv.x, o[3][0]); o[3][1] = fmaf(p3, vv.y, o[3][1]);
            o[3][2] = fmaf(p3, vv.z, o[3][2]); o[3][3] = fmaf(p3, vv.w, o[3][3]);
        }
    }

    const int b = bh / HEADS;
    const int h = bh % HEADS;
#pragma unroll
    for (int i = 0; i < 4; i++) {
        int n = q0 + (ty << 2) + i;
        if (n < NTOK) {
            float inv = 1.f / l_i[i];
            float4 r;
            r.x = o[i][0] * inv;
            r.y = o[i][1] * inv;
            r.z = o[i][2] * inv;
            r.w = o[i][3] * inv;
            *(float4*)(g_attn + (size_t)(b * NTOK + n) * CDIM + h * DHEAD + (tx << 2)) = r;
        }
    }
}

// ================================ launch ====================================
extern "C" void kernel_launch(void* const* d_in, const int* in_sizes, int n_in,
                              void* d_out, int out_size) {
    const float* x      = (const float*)d_in[0];
    const float* cosb   = (const float*)d_in[1];
    const float* sinb   = (const float*)d_in[2];
    const float* w_qkv  = (const float*)d_in[3];
    const float* b_qkv  = (const float*)d_in[4];
    const float* w_proj = (const float*)d_in[5];
    const float* b_proj = (const float*)d_in[6];
    float* out = (float*)d_out;

    cudaFuncSetAttribute(k_gemm_mma, cudaFuncAttributeMaxDynamicSharedMemorySize,
                         GT_SMEM);

    __nv_bfloat16 *pAh, *pAl, *pCh, *pCl, *pWqh, *pWql, *pWph, *pWpl;
    cudaGetSymbolAddress((void**)&pAh,  gAh);
    cudaGetSymbolAddress((void**)&pAl,  gAl);
    cudaGetSymbolAddress((void**)&pCh,  gCh);
    cudaGetSymbolAddress((void**)&pCl,  gCl);
    cudaGetSymbolAddress((void**)&pWqh, gWqh);
    cudaGetSymbolAddress((void**)&pWql, gWql);
    cudaGetSymbolAddress((void**)&pWph, gWph);
    cudaGetSymbolAddress((void**)&pWpl, gWpl);
    float *pqkv, *pattn;
    cudaGetSymbolAddress((void**)&pqkv,  g_qkv);
    cudaGetSymbolAddress((void**)&pattn, g_attn);

    const int n4 = MROWS * CDIM / 4;

    // 0) operand preparation (bf16 hi/lo splits; weights transposed)
    k_split4<<<(n4 + 255) / 256, 256>>>(x, pAh, pAl, n4);
    {
        dim3 g(QKVCOLS / 32, CDIM / 32), b(32, 8);
        k_wsplit_t<<<g, b>>>(w_qkv, pWqh, pWql, CDIM, QKVCOLS);
    }
    {
        dim3 g(CDIM / 32, CDIM / 32), b(32, 8);
        k_wsplit_t<<<g, b>>>(w_proj, pWph, pWpl, CDIM, CDIM);
    }

    // 1) QKV GEMM (HMMA bf16x3)
    {
        dim3 grid(QKVCOLS / 128, (MROWS + 127) / 128);
        k_gemm_mma<<<grid, 256, GT_SMEM>>>(pAh, pAl, pWqh, pWql, b_qkv, pqkv,
                                           MROWS, QKVCOLS);
    }
    // 2) RoPE + split/transpose
    {
        int total = BATCH * HEADS * NTOK * (DHEAD / 2);
        k_rope_split<<<(total + 255) / 256, 256>>>(cosb, sinb);
    }
    // 3) attention
    {
        dim3 grid((NTOK + 63) / 64, BHTOT);
        k_attn<<<grid, 256>>>();
    }
    // 4) output projection (HMMA bf16x3)
    k_split4<<<(n4 + 255) / 256, 256>>>(pattn, pCh, pCl, n4);
    {
        dim3 grid(CDIM / 128, (MROWS + 127) / 128);
        k_gemm_mma<<<grid, 256, GT_SMEM>>>(pCh, pCl, pWph, pWpl, b_proj, out,
                                           MROWS, CDIM);
    }
}

// round 10
// speedup vs baseline: 2.7171x; 1.7450x over previous
#include <cuda_runtime.h>
#include <cuda_bf16.h>
#include <cstdint>
#include <cstddef>

// Problem constants
#define BATCH   16
#define NTOK    577
#define CDIM    768
#define HEADS   12
#define DHEAD   64
#define MROWS   (BATCH * NTOK)          // 9232
#define QKVCOLS (3 * CDIM)              // 2304
#define BHTOT   (BATCH * HEADS)         // 192

// ===================== helpers ==============================================
__device__ __forceinline__ uint32_t smem_to_u32(const void* smem_ptr) {
    uint32_t addr;
    asm("{ .reg .u64 tmp; cvta.to.shared.u64 tmp, %1; cvt.u32.u64 %0, tmp; }"
        : "=r"(addr) : "l"(smem_ptr));
    return addr;
}

__device__ __forceinline__ void ldsm4(uint32_t* r, uint32_t addr) {
    asm volatile("ldmatrix.sync.aligned.m8n8.x4.shared.b16 {%0,%1,%2,%3}, [%4];"
                 : "=r"(r[0]), "=r"(r[1]), "=r"(r[2]), "=r"(r[3]) : "r"(addr));
}

__device__ __forceinline__ void ldsm4t(uint32_t* r, uint32_t addr) {
    asm volatile("ldmatrix.sync.aligned.m8n8.x4.trans.shared.b16 {%0,%1,%2,%3}, [%4];"
                 : "=r"(r[0]), "=r"(r[1]), "=r"(r[2]), "=r"(r[3]) : "r"(addr));
}

__device__ __forceinline__ void mma16816(float* c, const uint32_t* a,
                                         uint32_t b0, uint32_t b1) {
    asm volatile(
        "mma.sync.aligned.m16n8k16.row.col.f32.bf16.bf16.f32 "
        "{%0,%1,%2,%3}, {%4,%5,%6,%7}, {%8,%9}, {%0,%1,%2,%3};"
        : "+f"(c[0]), "+f"(c[1]), "+f"(c[2]), "+f"(c[3])
        : "r"(a[0]), "r"(a[1]), "r"(a[2]), "r"(a[3]), "r"(b0), "r"(b1));
}

// pack(lo, hi) -> bf16x2 register
__device__ __forceinline__ uint32_t pack_bf16x2(float lo, float hi) {
    uint32_t r;
    asm("cvt.rn.bf16x2.f32 %0, %1, %2;" : "=r"(r) : "f"(hi), "f"(lo));
    return r;
}

// ---------------- scratch (no allocations allowed -> device globals) --------
__device__ float g_qkv[(size_t)MROWS * QKVCOLS];              // (B*N, 3C)

// bf16 hi/lo split operands for tensor-core GEMMs
__device__ __nv_bfloat16 gAh[(size_t)MROWS * CDIM];           // x split
__device__ __nv_bfloat16 gAl[(size_t)MROWS * CDIM];
__device__ __nv_bfloat16 gCh[(size_t)MROWS * CDIM];           // attn-out split
__device__ __nv_bfloat16 gCl[(size_t)MROWS * CDIM];
__device__ __nv_bfloat16 gWqh[(size_t)QKVCOLS * CDIM];        // w_qkv^T split
__device__ __nv_bfloat16 gWql[(size_t)QKVCOLS * CDIM];
__device__ __nv_bfloat16 gWph[(size_t)CDIM * CDIM];           // w_proj^T split
__device__ __nv_bfloat16 gWpl[(size_t)CDIM * CDIM];

// bf16 hi/lo Q/K/V, (B*H, N, D)
__device__ __nv_bfloat16 gQh[(size_t)BHTOT * NTOK * DHEAD];
__device__ __nv_bfloat16 gQl[(size_t)BHTOT * NTOK * DHEAD];
__device__ __nv_bfloat16 gKh[(size_t)BHTOT * NTOK * DHEAD];
__device__ __nv_bfloat16 gKl[(size_t)BHTOT * NTOK * DHEAD];
__device__ __nv_bfloat16 gVh[(size_t)BHTOT * NTOK * DHEAD];
__device__ __nv_bfloat16 gVl[(size_t)BHTOT * NTOK * DHEAD];

// ==================== fp32 -> bf16 hi/lo split (row-major) ==================
__global__ __launch_bounds__(256) void k_split4(const float* __restrict__ in,
                                                __nv_bfloat16* __restrict__ oh,
                                                __nv_bfloat16* __restrict__ ol,
                                                int n4) {
    int i = blockIdx.x * blockDim.x + threadIdx.x;
    if (i >= n4) return;
    float4 v = ((const float4*)in)[i];
    float f[4] = {v.x, v.y, v.z, v.w};
    __align__(8) __nv_bfloat16 h[4];
    __align__(8) __nv_bfloat16 l[4];
#pragma unroll
    for (int j = 0; j < 4; j++) {
        h[j] = __float2bfloat16_rn(f[j]);
        l[j] = __float2bfloat16_rn(f[j] - __bfloat162float(h[j]));
    }
    *(uint2*)(oh + 4 * (size_t)i) = *(uint2*)h;
    *(uint2*)(ol + 4 * (size_t)i) = *(uint2*)l;
}

// ============ W[K][N] -> Wt_hi/Wt_lo[N][K] bf16 (transpose + split) =========
__global__ __launch_bounds__(256) void k_wsplit_t(const float* __restrict__ w,
                                                  __nv_bfloat16* __restrict__ oh,
                                                  __nv_bfloat16* __restrict__ ol,
                                                  int K, int N) {
    __shared__ float t[32][33];
    int n0 = blockIdx.x * 32, k0 = blockIdx.y * 32;
    int tx = threadIdx.x, ty = threadIdx.y;
#pragma unroll
    for (int j = 0; j < 32; j += 8)
        t[ty + j][tx] = w[(size_t)(k0 + ty + j) * N + n0 + tx];
    __syncthreads();
#pragma unroll
    for (int j = 0; j < 32; j += 8) {
        float v = t[tx][ty + j];
        int n = n0 + ty + j, k = k0 + tx;
        __nv_bfloat16 h = __float2bfloat16_rn(v);
        __nv_bfloat16 l = __float2bfloat16_rn(v - __bfloat162float(h));
        oh[(size_t)n * K + k] = h;
        ol[(size_t)n * K + k] = l;
    }
}

// =================== HMMA bf16x3 GEMM: C = A@B + bias =======================
#define GT_TILE 8192                    // 128 x 32 bf16
#define GT_BUF  (4 * GT_TILE)           // 32KB / stage
#define GT_SMEM (2 * GT_BUF)            // 64KB

__global__ __launch_bounds__(256) void k_gemm_mma(
    const __nv_bfloat16* __restrict__ Ah, const __nv_bfloat16* __restrict__ Al,
    const __nv_bfloat16* __restrict__ Bh, const __nv_bfloat16* __restrict__ Bl,
    const float* __restrict__ bias, float* __restrict__ C, int M, int N) {
    extern __shared__ __align__(128) char smem[];
    const uint32_t sbase = smem_to_u32(smem);

    const int tid  = threadIdx.x;
    const int lane = tid & 31;
    const int wid  = tid >> 5;
    const int wm   = wid >> 2;
    const int wn   = wid & 3;
    const int block_row = blockIdx.y * 128;
    const int block_col = blockIdx.x * 128;

    const int u0 = tid, u1 = tid + 256;
    const int r0 = u0 >> 2, c0 = u0 & 3;
    const int r1 = u1 >> 2, c1 = u1 & 3;
    const uint32_t so0 = (uint32_t)(r0 * 64 + ((c0 ^ ((r0 >> 1) & 3)) << 4));
    const uint32_t so1 = (uint32_t)(r1 * 64 + ((c1 ^ ((r1 >> 1) & 3)) << 4));
    const bool a0ok = (block_row + r0) < M;
    const bool a1ok = (block_row + r1) < M;
    const size_t gA0 = (size_t)(block_row + r0) * CDIM + c0 * 8;
    const size_t gA1 = (size_t)(block_row + r1) * CDIM + c1 * 8;
    const size_t gB0 = (size_t)(block_col + r0) * CDIM + c0 * 8;
    const size_t gB1 = (size_t)(block_col + r1) * CDIM + c1 * 8;

    const int lrow = lane & 15;
    const int lkc  = lane >> 4;
    uint32_t offA[2][4], offB[2][2];
#pragma unroll
    for (int kk2 = 0; kk2 < 2; kk2++) {
        int cc = kk2 * 2 + lkc;
#pragma unroll
        for (int mi = 0; mi < 4; mi++) {
            int rr = wm * 64 + mi * 16 + lrow;
            offA[kk2][mi] = (uint32_t)(rr * 64 + ((cc ^ ((rr >> 1) & 3)) << 4));
        }
#pragma unroll
        for (int nb = 0; nb < 2; nb++) {
            int rr = wn * 32 + nb * 16 + lrow;
            offB[kk2][nb] = (uint32_t)(rr * 64 + ((cc ^ ((rr >> 1) & 3)) << 4));
        }
    }

    float acc[4][4][4];
#pragma unroll
    for (int mi = 0; mi < 4; mi++)
#pragma unroll
        for (int ni = 0; ni < 4; ni++)
#pragma unroll
            for (int j = 0; j < 4; j++) acc[mi][ni][j] = 0.f;

    const int NSTAGE = CDIM / 32;

    {
        char* b = smem;
        uint4 z = make_uint4(0, 0, 0, 0);
        *(uint4*)(b + so0)               = a0ok ? *(const uint4*)(Ah + gA0) : z;
        *(uint4*)(b + so1)               = a1ok ? *(const uint4*)(Ah + gA1) : z;
        *(uint4*)(b + GT_TILE + so0)     = a0ok ? *(const uint4*)(Al + gA0) : z;
        *(uint4*)(b + GT_TILE + so1)     = a1ok ? *(const uint4*)(Al + gA1) : z;
        *(uint4*)(b + 2 * GT_TILE + so0) = *(const uint4*)(Bh + gB0);
        *(uint4*)(b + 2 * GT_TILE + so1) = *(const uint4*)(Bh + gB1);
        *(uint4*)(b + 3 * GT_TILE + so0) = *(const uint4*)(Bl + gB0);
        *(uint4*)(b + 3 * GT_TILE + so1) = *(const uint4*)(Bl + gB1);
    }
    __syncthreads();

    for (int s = 0; s < NSTAGE; s++) {
        const int bsel = s & 1;
        const uint32_t tbase = sbase + bsel * GT_BUF;

        uint4 p[8];
        const bool more = (s + 1) < NSTAGE;
        if (more) {
            const int ko = (s + 1) * 32;
            uint4 z = make_uint4(0, 0, 0, 0);
            p[0] = a0ok ? *(const uint4*)(Ah + gA0 + ko) : z;
            p[1] = a0ok ? *(const uint4*)(Al + gA0 + ko) : z;
            p[2] = *(const uint4*)(Bh + gB0 + ko);
            p[3] = *(const uint4*)(Bl + gB0 + ko);
            p[4] = a1ok ? *(const uint4*)(Ah + gA1 + ko) : z;
            p[5] = a1ok ? *(const uint4*)(Al + gA1 + ko) : z;
            p[6] = *(const uint4*)(Bh + gB1 + ko);
            p[7] = *(const uint4*)(Bl + gB1 + ko);
        }

#pragma unroll
        for (int kk2 = 0; kk2 < 2; kk2++) {
            uint32_t ah[4][4], al[4][4], bh[2][4], bl[2][4];
#pragma unroll
            for (int mi = 0; mi < 4; mi++) {
                ldsm4(ah[mi], tbase + offA[kk2][mi]);
                ldsm4(al[mi], tbase + GT_TILE + offA[kk2][mi]);
            }
#pragma unroll
            for (int nb = 0; nb < 2; nb++) {
                ldsm4(bh[nb], tbase + 2 * GT_TILE + offB[kk2][nb]);
                ldsm4(bl[nb], tbase + 3 * GT_TILE + offB[kk2][nb]);
            }
#pragma unroll
            for (int mi = 0; mi < 4; mi++) {
#pragma unroll
                for (int ni = 0; ni < 4; ni++) {
                    const int nb = ni >> 1;
                    const int nsub = ni & 1;
                    uint32_t bh0 = bh[nb][nsub], bh1 = bh[nb][nsub + 2];
                    uint32_t bl0 = bl[nb][nsub], bl1 = bl[nb][nsub + 2];
                    mma16816(acc[mi][ni], ah[mi], bh0, bh1);
                    mma16816(acc[mi][ni], ah[mi], bl0, bl1);
                    mma16816(acc[mi][ni], al[mi], bh0, bh1);
                }
            }
        }

        if (more) {
            __syncthreads();
            char* b = smem + (bsel ^ 1) * GT_BUF;
            *(uint4*)(b + so0)               = p[0];
            *(uint4*)(b + GT_TILE + so0)     = p[1];
            *(uint4*)(b + 2 * GT_TILE + so0) = p[2];
            *(uint4*)(b + 3 * GT_TILE + so0) = p[3];
            *(uint4*)(b + so1)               = p[4];
            *(uint4*)(b + GT_TILE + so1)     = p[5];
            *(uint4*)(b + 2 * GT_TILE + so1) = p[6];
            *(uint4*)(b + 3 * GT_TILE + so1) = p[7];
            __syncthreads();
        }
    }

    const int erow = lane >> 2;
    const int ecol = (lane & 3) << 1;
#pragma unroll
    for (int mi = 0; mi < 4; mi++) {
#pragma unroll
        for (int ni = 0; ni < 4; ni++) {
            int r = block_row + wm * 64 + mi * 16 + erow;
            int col = block_col + wn * 32 + ni * 8 + ecol;
            float2 bv = *(const float2*)(bias + col);
            if (r < M) {
                float2 o = make_float2(acc[mi][ni][0] + bv.x,
                                       acc[mi][ni][1] + bv.y);
                *(float2*)(C + (size_t)r * N + col) = o;
            }
            if (r + 8 < M) {
                float2 o = make_float2(acc[mi][ni][2] + bv.x,
                                       acc[mi][ni][3] + bv.y);
                *(float2*)(C + (size_t)(r + 8) * N + col) = o;
            }
        }
    }
}

// ====== RoPE + split (B,N,3,H,D) -> Q/K/V (B*H, N, D) bf16 hi/lo ===========
__global__ __launch_bounds__(256) void k_rope_split(const float* __restrict__ cosb,
                                                    const float* __restrict__ sinb) {
    int idx = blockIdx.x * blockDim.x + threadIdx.x;
    const int total = BATCH * HEADS * NTOK * (DHEAD / 2);
    if (idx >= total) return;

    int d2 = idx & 31;
    int n  = (idx >> 5) % NTOK;
    int h  = (idx / (32 * NTOK)) % HEADS;
    int b  = idx / (32 * NTOK * HEADS);

    size_t base = (size_t)(b * NTOK + n) * QKVCOLS + h * DHEAD + (d2 << 1);
    float2 q = *(const float2*)(g_qkv + base);
    float2 k = *(const float2*)(g_qkv + base + CDIM);
    float2 v = *(const float2*)(g_qkv + base + 2 * CDIM);

    if (n > 0) {
        float c = cosb[(size_t)(n - 1) * 32 + d2];
        float s = sinb[(size_t)(n - 1) * 32 + d2];
        float2 qr, kr;
        qr.x = q.x * c - q.y * s;  qr.y = q.x * s + q.y * c;
        kr.x = k.x * c - k.y * s;  kr.y = k.x * s + k.y * c;
        q = qr; k = kr;
    }

    size_t o = ((size_t)(b * HEADS + h) * NTOK + n) * DHEAD + (d2 << 1);

    float qhx = __bfloat162float(__float2bfloat16_rn(q.x));
    float qhy = __bfloat162float(__float2bfloat16_rn(q.y));
    float khx = __bfloat162float(__float2bfloat16_rn(k.x));
    float khy = __bfloat162float(__float2bfloat16_rn(k.y));
    float vhx = __bfloat162float(__float2bfloat16_rn(v.x));
    float vhy = __bfloat162float(__float2bfloat16_rn(v.y));

    *(uint32_t*)(gQh + o) = pack_bf16x2(qhx, qhy);
    *(uint32_t*)(gQl + o) = pack_bf16x2(q.x - qhx, q.y - qhy);
    *(uint32_t*)(gKh + o) = pack_bf16x2(khx, khy);
    *(uint32_t*)(gKl + o) = pack_bf16x2(k.x - khx, k.y - khy);
    *(uint32_t*)(gVh + o) = pack_bf16x2(vhx, vhy);
    *(uint32_t*)(gVl + o) = pack_bf16x2(v.x - vhx, v.y - vhy);
}

// ============== Flash attention on HMMA, bf16x3, 128 q-rows/CTA =============
// 8 warps, warp tile m16 x n64 (complete rows => warp-local softmax).
// smem (dynamic, 64KB): Qh,Ql [128][64]; Kh,Kl,Vh,Vl [64][64].
// Swizzle: 16B chunk c of row r stored at (c ^ (r&7)).
#define ASM_QH 0
#define ASM_QL 16384
#define ASM_KH 32768
#define ASM_KL 40960
#define ASM_VH 49152
#define ASM_VL 57344
#define ASM_TOTAL 65536

__global__ __launch_bounds__(256) void k_attn_mma() {
    extern __shared__ __align__(128) char asmem[];
    const uint32_t sb = smem_to_u32(asmem);
    const int tid = threadIdx.x;
    const int lane = tid & 31;
    const int wid = tid >> 5;
    const int bh = blockIdx.y;
    const int q0 = blockIdx.x * 128;
    const size_t gbase = (size_t)bh * NTOK * DHEAD;

    // ---- load Q tile (persistent): 128 rows x 8 chunks ----
#pragma unroll
    for (int i = 0; i < 4; i++) {
        int u = tid + (i << 8);
        int r = u >> 3, c = u & 7;
        uint32_t so = (uint32_t)(r * 128 + ((c ^ (r & 7)) << 4));
        uint4 zh = make_uint4(0, 0, 0, 0), zl = zh;
        if (q0 + r < NTOK) {
            size_t g = gbase + (size_t)(q0 + r) * DHEAD + c * 8;
            zh = *(const uint4*)(gQh + g);
            zl = *(const uint4*)(gQl + g);
        }
        *(uint4*)(asmem + ASM_QH + so) = zh;
        *(uint4*)(asmem + ASM_QL + so) = zl;
    }

    const int m0 = wid * 16;
    const int alr = m0 + (lane & 15);
    const int akc = lane >> 4;
    uint32_t offQ[4];
#pragma unroll
    for (int k16 = 0; k16 < 4; k16++)
        offQ[k16] = (uint32_t)(alr * 128 + (((2 * k16 + akc) ^ (alr & 7)) << 4));

    float m_[2] = {-1e30f, -1e30f};
    float l_[2] = {0.f, 0.f};
    float o[8][4];
#pragma unroll
    for (int t = 0; t < 8; t++)
#pragma unroll
        for (int j = 0; j < 4; j++) o[t][j] = 0.f;

    const float scale = 0.125f;

    for (int kt = 0; kt < 10; kt++) {
        const int k0 = kt * 64;
        __syncthreads();   // prior iter done with K/V (iter0: orders Q stores)

        // ---- load K/V tiles: 64 rows x 8 chunks each ----
#pragma unroll
        for (int i = 0; i < 2; i++) {
            int u = tid + (i << 8);
            int r = u >> 3, c = u & 7;
            uint32_t so = (uint32_t)(r * 128 + ((c ^ (r & 7)) << 4));
            uint4 kh = make_uint4(0, 0, 0, 0), kl = kh, vh = kh, vl = kh;
            if (k0 + r < NTOK) {
                size_t g = gbase + (size_t)(k0 + r) * DHEAD + c * 8;
                kh = *(const uint4*)(gKh + g);
                kl = *(const uint4*)(gKl + g);
                vh = *(const uint4*)(gVh + g);
                vl = *(const uint4*)(gVl + g);
            }
            *(uint4*)(asmem + ASM_KH + so) = kh;
            *(uint4*)(asmem + ASM_KL + so) = kl;
            *(uint4*)(asmem + ASM_VH + so) = vh;
            *(uint4*)(asmem + ASM_VL + so) = vl;
        }
        __syncthreads();

        // ---- S = Q @ K^T (x3 split) ----
        float s[8][4];
#pragma unroll
        for (int t = 0; t < 8; t++)
#pragma unroll
            for (int j = 0; j < 4; j++) s[t][j] = 0.f;

#pragma unroll
        for (int k16 = 0; k16 < 4; k16++) {
            uint32_t qh[4], ql[4];
            ldsm4(qh, sb + ASM_QH + offQ[k16]);
            ldsm4(ql, sb + ASM_QL + offQ[k16]);
            uint32_t kh[4][4], kl[4][4];
#pragma unroll
            for (int nb = 0; nb < 4; nb++) {
                int krow = nb * 16 + (lane & 15);
                uint32_t off = (uint32_t)(krow * 128 +
                                (((2 * k16 + akc) ^ (krow & 7)) << 4));
                ldsm4(kh[nb], sb + ASM_KH + off);
                ldsm4(kl[nb], sb + ASM_KL + off);
            }
#pragma unroll
            for (int nb = 0; nb < 4; nb++) {
#pragma unroll
                for (int nsub = 0; nsub < 2; nsub++) {
                    int t = nb * 2 + nsub;
                    uint32_t bh0 = kh[nb][nsub], bh1 = kh[nb][nsub + 2];
                    uint32_t bl0 = kl[nb][nsub], bl1 = kl[nb][nsub + 2];
                    mma16816(s[t], qh, bh0, bh1);
                    mma16816(s[t], qh, bl0, bl1);
                    mma16816(s[t], ql, bh0, bh1);
                }
            }
        }

        // ---- online softmax (warp-local rows) ----
        const bool lastt = (k0 + 64 > NTOK);
        float fi[2];
#pragma unroll
        for (int j = 0; j < 2; j++) {
            float rm = -1e30f;
#pragma unroll
            for (int t = 0; t < 8; t++) {
#pragma unroll
                for (int c = 0; c < 2; c++) {
                    float v = s[t][j * 2 + c] * scale;
                    if (lastt) {
                        int col = k0 + t * 8 + ((lane & 3) << 1) + c;
                        if (col >= NTOK) v = -1e30f;
                    }
                    s[t][j * 2 + c] = v;
                    rm = fmaxf(rm, v);
                }
            }
            rm = fmaxf(rm, __shfl_xor_sync(0xffffffffu, rm, 1));
            rm = fmaxf(rm, __shfl_xor_sync(0xffffffffu, rm, 2));
            float mn = fmaxf(m_[j], rm);
            fi[j] = __expf(m_[j] - mn);
            m_[j] = mn;
            float rs = 0.f;
#pragma unroll
            for (int t = 0; t < 8; t++) {
#pragma unroll
                for (int c = 0; c < 2; c++) {
                    float p = __expf(s[t][j * 2 + c] - mn);
                    s[t][j * 2 + c] = p;
                    rs += p;
                }
            }
            rs += __shfl_xor_sync(0xffffffffu, rs, 1);
            rs += __shfl_xor_sync(0xffffffffu, rs, 2);
            l_[j] = l_[j] * fi[j] + rs;
        }
#pragma unroll
        for (int t = 0; t < 8; t++) {
            o[t][0] *= fi[0]; o[t][1] *= fi[0];
            o[t][2] *= fi[1]; o[t][3] *= fi[1];
        }

        // ---- O += P @ V (x3 split), P frags built in registers ----
#pragma unroll
        for (int t2 = 0; t2 < 4; t2++) {
            uint32_t ph[4], pl[4];
#pragma unroll
            for (int idx = 0; idx < 4; idx++) {
                int t = 2 * t2 + (idx >> 1);
                int j = idx & 1;
                float x0 = s[t][j * 2 + 0];
                float x1 = s[t][j * 2 + 1];
                float h0 = __bfloat162float(__float2bfloat16_rn(x0));
                float h1 = __bfloat162float(__float2bfloat16_rn(x1));
                ph[idx] = pack_bf16x2(h0, h1);
                pl[idx] = pack_bf16x2(x0 - h0, x1 - h1);
            }
            const int vm = lane >> 3;
            const int vk = t2 * 16 + ((vm & 1) << 3) + (lane & 7);
#pragma unroll
            for (int nb = 0; nb < 4; nb++) {
                int vc = nb * 2 + (vm >> 1);
                uint32_t off = (uint32_t)(vk * 128 + ((vc ^ (vk & 7)) << 4));
                uint32_t vh[4], vl[4];
                ldsm4t(vh, sb + ASM_VH + off);
                ldsm4t(vl, sb + ASM_VL + off);
                mma16816(o[nb * 2 + 0], ph, vh[0], vh[1]);
                mma16816(o[nb * 2 + 0], ph, vl[0], vl[1]);
                mma16816(o[nb * 2 + 0], pl, vh[0], vh[1]);
                mma16816(o[nb * 2 + 1], ph, vh[2], vh[3]);
                mma16816(o[nb * 2 + 1], ph, vl[2], vl[3]);
                mma16816(o[nb * 2 + 1], pl, vh[2], vh[3]);
            }
        }
    }

    // ---- epilogue: write bf16 hi/lo proj operands ----
    const int b = bh / HEADS;
    const int h = bh % HEADS;
#pragma unroll
    for (int j = 0; j < 2; j++) {
        int n = q0 + m0 + (lane >> 2) + j * 8;
        if (n < NTOK) {
            float inv = 1.f / l_[j];
            size_t gr = (size_t)(b * NTOK + n) * CDIM + h * DHEAD;
#pragma unroll
            for (int t = 0; t < 8; t++) {
                int col = t * 8 + ((lane & 3) << 1);
                float x0 = o[t][j * 2 + 0] * inv;
                float x1 = o[t][j * 2 + 1] * inv;
                float h0 = __bfloat162float(__float2bfloat16_rn(x0));
                float h1 = __bfloat162float(__float2bfloat16_rn(x1));
                *(uint32_t*)(gCh + gr + col) = pack_bf16x2(h0, h1);
                *(uint32_t*)(gCl + gr + col) = pack_bf16x2(x0 - h0, x1 - h1);
            }
        }
    }
}

// ================================ launch ====================================
extern "C" void kernel_launch(void* const* d_in, const int* in_sizes, int n_in,
                              void* d_out, int out_size) {
    const float* x      = (const float*)d_in[0];
    const float* cosb   = (const float*)d_in[1];
    const float* sinb   = (const float*)d_in[2];
    const float* w_qkv  = (const float*)d_in[3];
    const float* b_qkv  = (const float*)d_in[4];
    const float* w_proj = (const float*)d_in[5];
    const float* b_proj = (const float*)d_in[6];
    float* out = (float*)d_out;

    cudaFuncSetAttribute(k_gemm_mma, cudaFuncAttributeMaxDynamicSharedMemorySize,
                         GT_SMEM);
    cudaFuncSetAttribute(k_attn_mma, cudaFuncAttributeMaxDynamicSharedMemorySize,
                         ASM_TOTAL);

    __nv_bfloat16 *pAh, *pAl, *pCh, *pCl, *pWqh, *pWql, *pWph, *pWpl;
    cudaGetSymbolAddress((void**)&pAh,  gAh);
    cudaGetSymbolAddress((void**)&pAl,  gAl);
    cudaGetSymbolAddress((void**)&pCh,  gCh);
    cudaGetSymbolAddress((void**)&pCl,  gCl);
    cudaGetSymbolAddress((void**)&pWqh, gWqh);
    cudaGetSymbolAddress((void**)&pWql, gWql);
    cudaGetSymbolAddress((void**)&pWph, gWph);
    cudaGetSymbolAddress((void**)&pWpl, gWpl);
    float* pqkv;
    cudaGetSymbolAddress((void**)&pqkv, g_qkv);

    const int n4 = MROWS * CDIM / 4;

    // 0) operand preparation
    k_split4<<<(n4 + 255) / 256, 256>>>(x, pAh, pAl, n4);
    {
        dim3 g(QKVCOLS / 32, CDIM / 32), b(32, 8);
        k_wsplit_t<<<g, b>>>(w_qkv, pWqh, pWql, CDIM, QKVCOLS);
    }
    {
        dim3 g(CDIM / 32, CDIM / 32), b(32, 8);
        k_wsplit_t<<<g, b>>>(w_proj, pWph, pWpl, CDIM, CDIM);
    }

    // 1) QKV GEMM (HMMA bf16x3)
    {
        dim3 grid(QKVCOLS / 128, (MROWS + 127) / 128);
        k_gemm_mma<<<grid, 256, GT_SMEM>>>(pAh, pAl, pWqh, pWql, b_qkv, pqkv,
                                           MROWS, QKVCOLS);
    }
    // 2) RoPE + split to bf16 hi/lo Q/K/V
    {
        int total = BATCH * HEADS * NTOK * (DHEAD / 2);
        k_rope_split<<<(total + 255) / 256, 256>>>(cosb, sinb);
    }
    // 3) attention (HMMA bf16x3) — writes gCh/gCl directly
    {
        dim3 grid((NTOK + 127) / 128, BHTOT);
        k_attn_mma<<<grid, 256, ASM_TOTAL>>>();
    }
    // 4) output projection (HMMA bf16x3)
    {
        dim3 grid(CDIM / 128, (MROWS + 127) / 128);
        k_gemm_mma<<<grid, 256, GT_SMEM>>>(pCh, pCl, pWph, pWpl, b_proj, out,
                                           MROWS, CDIM);
    }
}

// round 11
// speedup vs baseline: 3.1850x; 1.1722x over previous
#include <cuda_runtime.h>
#include <cuda_bf16.h>
#include <cstdint>
#include <cstddef>

// Problem constants
#define BATCH   16
#define NTOK    577
#define CDIM    768
#define HEADS   12
#define DHEAD   64
#define MROWS   (BATCH * NTOK)          // 9232
#define QKVCOLS (3 * CDIM)              // 2304
#define BHTOT   (BATCH * HEADS)         // 192

// ===================== helpers ==============================================
__device__ __forceinline__ uint32_t smem_to_u32(const void* smem_ptr) {
    uint32_t addr;
    asm("{ .reg .u64 tmp; cvta.to.shared.u64 tmp, %1; cvt.u32.u64 %0, tmp; }"
        : "=r"(addr) : "l"(smem_ptr));
    return addr;
}

__device__ __forceinline__ void ldsm4(uint32_t* r, uint32_t addr) {
    asm volatile("ldmatrix.sync.aligned.m8n8.x4.shared.b16 {%0,%1,%2,%3}, [%4];"
                 : "=r"(r[0]), "=r"(r[1]), "=r"(r[2]), "=r"(r[3]) : "r"(addr));
}

__device__ __forceinline__ void ldsm4t(uint32_t* r, uint32_t addr) {
    asm volatile("ldmatrix.sync.aligned.m8n8.x4.trans.shared.b16 {%0,%1,%2,%3}, [%4];"
                 : "=r"(r[0]), "=r"(r[1]), "=r"(r[2]), "=r"(r[3]) : "r"(addr));
}

__device__ __forceinline__ void mma16816(float* c, const uint32_t* a,
                                         uint32_t b0, uint32_t b1) {
    asm volatile(
        "mma.sync.aligned.m16n8k16.row.col.f32.bf16.bf16.f32 "
        "{%0,%1,%2,%3}, {%4,%5,%6,%7}, {%8,%9}, {%0,%1,%2,%3};"
        : "+f"(c[0]), "+f"(c[1]), "+f"(c[2]), "+f"(c[3])
        : "r"(a[0]), "r"(a[1]), "r"(a[2]), "r"(a[3]), "r"(b0), "r"(b1));
}

// pack(lo, hi) -> bf16x2 register
__device__ __forceinline__ uint32_t pack_bf16x2(float lo, float hi) {
    uint32_t r;
    asm("cvt.rn.bf16x2.f32 %0, %1, %2;" : "=r"(r) : "f"(hi), "f"(lo));
    return r;
}

// 16B async copy; pred=false => zero-fill (reads 0 bytes)
__device__ __forceinline__ void cp_async16(uint32_t dst, const void* src, bool pred) {
    int sz = pred ? 16 : 0;
    asm volatile("cp.async.cg.shared.global [%0], [%1], 16, %2;"
                 :: "r"(dst), "l"(src), "r"(sz) : "memory");
}
__device__ __forceinline__ void cp_commit() {
    asm volatile("cp.async.commit_group;" ::: "memory");
}
template <int N>
__device__ __forceinline__ void cp_wait() {
    asm volatile("cp.async.wait_group %0;" :: "n"(N) : "memory");
}

// ---------------- scratch (no allocations allowed -> device globals) --------
__device__ float g_qkv[(size_t)MROWS * QKVCOLS];              // (B*N, 3C)

// bf16 hi/lo split operands for tensor-core GEMMs
__device__ __nv_bfloat16 gAh[(size_t)MROWS * CDIM];           // x split
__device__ __nv_bfloat16 gAl[(size_t)MROWS * CDIM];
__device__ __nv_bfloat16 gCh[(size_t)MROWS * CDIM];           // attn-out split
__device__ __nv_bfloat16 gCl[(size_t)MROWS * CDIM];
__device__ __nv_bfloat16 gWqh[(size_t)QKVCOLS * CDIM];        // w_qkv^T split
__device__ __nv_bfloat16 gWql[(size_t)QKVCOLS * CDIM];
__device__ __nv_bfloat16 gWph[(size_t)CDIM * CDIM];           // w_proj^T split
__device__ __nv_bfloat16 gWpl[(size_t)CDIM * CDIM];

// bf16 hi/lo Q/K/V, (B*H, N, D)
__device__ __nv_bfloat16 gQh[(size_t)BHTOT * NTOK * DHEAD];
__device__ __nv_bfloat16 gQl[(size_t)BHTOT * NTOK * DHEAD];
__device__ __nv_bfloat16 gKh[(size_t)BHTOT * NTOK * DHEAD];
__device__ __nv_bfloat16 gKl[(size_t)BHTOT * NTOK * DHEAD];
__device__ __nv_bfloat16 gVh[(size_t)BHTOT * NTOK * DHEAD];
__device__ __nv_bfloat16 gVl[(size_t)BHTOT * NTOK * DHEAD];

// ==================== fp32 -> bf16 hi/lo split (row-major) ==================
__global__ __launch_bounds__(256) void k_split4(const float* __restrict__ in,
                                                __nv_bfloat16* __restrict__ oh,
                                                __nv_bfloat16* __restrict__ ol,
                                                int n4) {
    int i = blockIdx.x * blockDim.x + threadIdx.x;
    if (i >= n4) return;
    float4 v = ((const float4*)in)[i];
    float f[4] = {v.x, v.y, v.z, v.w};
    __align__(8) __nv_bfloat16 h[4];
    __align__(8) __nv_bfloat16 l[4];
#pragma unroll
    for (int j = 0; j < 4; j++) {
        h[j] = __float2bfloat16_rn(f[j]);
        l[j] = __float2bfloat16_rn(f[j] - __bfloat162float(h[j]));
    }
    *(uint2*)(oh + 4 * (size_t)i) = *(uint2*)h;
    *(uint2*)(ol + 4 * (size_t)i) = *(uint2*)l;
}

// ============ W[K][N] -> Wt_hi/Wt_lo[N][K] bf16 (transpose + split) =========
__global__ __launch_bounds__(256) void k_wsplit_t(const float* __restrict__ w,
                                                  __nv_bfloat16* __restrict__ oh,
                                                  __nv_bfloat16* __restrict__ ol,
                                                  int K, int N) {
    __shared__ float t[32][33];
    int n0 = blockIdx.x * 32, k0 = blockIdx.y * 32;
    int tx = threadIdx.x, ty = threadIdx.y;
#pragma unroll
    for (int j = 0; j < 32; j += 8)
        t[ty + j][tx] = w[(size_t)(k0 + ty + j) * N + n0 + tx];
    __syncthreads();
#pragma unroll
    for (int j = 0; j < 32; j += 8) {
        float v = t[tx][ty + j];
        int n = n0 + ty + j, k = k0 + tx;
        __nv_bfloat16 h = __float2bfloat16_rn(v);
        __nv_bfloat16 l = __float2bfloat16_rn(v - __bfloat162float(h));
        oh[(size_t)n * K + k] = h;
        ol[(size_t)n * K + k] = l;
    }
}

// =================== HMMA bf16x3 GEMM: C = A@B + bias =======================
// 3-stage cp.async pipeline; 2 CTAs/SM. Tile 128x128, BK=32, 8 warps (2x4).
#define GT_TILE 8192                    // 128 x 32 bf16
#define GT_BUF  (4 * GT_TILE)           // 32KB / stage (Ah,Al,Bh,Bl)
#define GT_SMEM (3 * GT_BUF)            // 96KB, 3 stages

__global__ __launch_bounds__(256, 2) void k_gemm_mma(
    const __nv_bfloat16* __restrict__ Ah, const __nv_bfloat16* __restrict__ Al,
    const __nv_bfloat16* __restrict__ Bh, const __nv_bfloat16* __restrict__ Bl,
    const float* __restrict__ bias, float* __restrict__ C, int M, int N) {
    extern __shared__ __align__(128) char smem[];
    const uint32_t sbase = smem_to_u32(smem);

    const int tid  = threadIdx.x;
    const int lane = tid & 31;
    const int wid  = tid >> 5;
    const int wm   = wid >> 2;
    const int wn   = wid & 3;
    const int block_row = blockIdx.y * 128;
    const int block_col = blockIdx.x * 128;

    // global->smem chunk mapping (2 chunks per thread per tile)
    const int u0 = tid, u1 = tid + 256;
    const int r0 = u0 >> 2, c0 = u0 & 3;
    const int r1 = u1 >> 2, c1 = u1 & 3;
    const uint32_t so0 = (uint32_t)(r0 * 64 + ((c0 ^ ((r0 >> 1) & 3)) << 4));
    const uint32_t so1 = (uint32_t)(r1 * 64 + ((c1 ^ ((r1 >> 1) & 3)) << 4));
    const bool a0ok = (block_row + r0) < M;
    const bool a1ok = (block_row + r1) < M;
    // clamp rows so OOB cp.async (size 0) still has an in-range address
    const int ar0 = a0ok ? (block_row + r0) : (M - 1);
    const int ar1 = a1ok ? (block_row + r1) : (M - 1);
    const size_t gA0 = (size_t)ar0 * CDIM + c0 * 8;
    const size_t gA1 = (size_t)ar1 * CDIM + c1 * 8;
    const size_t gB0 = (size_t)(block_col + r0) * CDIM + c0 * 8;
    const size_t gB1 = (size_t)(block_col + r1) * CDIM + c1 * 8;

    // ldmatrix source offsets (loop invariant)
    const int lrow = lane & 15;
    const int lkc  = lane >> 4;
    uint32_t offA[2][4], offB[2][2];
#pragma unroll
    for (int kk2 = 0; kk2 < 2; kk2++) {
        int cc = kk2 * 2 + lkc;
#pragma unroll
        for (int mi = 0; mi < 4; mi++) {
            int rr = wm * 64 + mi * 16 + lrow;
            offA[kk2][mi] = (uint32_t)(rr * 64 + ((cc ^ ((rr >> 1) & 3)) << 4));
        }
#pragma unroll
        for (int nb = 0; nb < 2; nb++) {
            int rr = wn * 32 + nb * 16 + lrow;
            offB[kk2][nb] = (uint32_t)(rr * 64 + ((cc ^ ((rr >> 1) & 3)) << 4));
        }
    }

    float acc[4][4][4];
#pragma unroll
    for (int mi = 0; mi < 4; mi++)
#pragma unroll
        for (int ni = 0; ni < 4; ni++)
#pragma unroll
            for (int j = 0; j < 4; j++) acc[mi][ni][j] = 0.f;

    const int NSTAGE = CDIM / 32;        // 24

    // issue one stage's copies into buffer `buf`
    auto issue = [&](int s, int buf) {
        const int ko = s * 32;
        const uint32_t b = sbase + (uint32_t)buf * GT_BUF;
        cp_async16(b + so0,               Ah + gA0 + ko, a0ok);
        cp_async16(b + so1,               Ah + gA1 + ko, a1ok);
        cp_async16(b + GT_TILE + so0,     Al + gA0 + ko, a0ok);
        cp_async16(b + GT_TILE + so1,     Al + gA1 + ko, a1ok);
        cp_async16(b + 2 * GT_TILE + so0, Bh + gB0 + ko, true);
        cp_async16(b + 2 * GT_TILE + so1, Bh + gB1 + ko, true);
        cp_async16(b + 3 * GT_TILE + so0, Bl + gB0 + ko, true);
        cp_async16(b + 3 * GT_TILE + so1, Bl + gB1 + ko, true);
    };

    issue(0, 0); cp_commit();
    issue(1, 1); cp_commit();

    int buf = 0;
    for (int s = 0; s < NSTAGE; s++) {
        cp_wait<1>();          // stage s landed (newest may be in flight)
        __syncthreads();       // visible to all; all warps done with stage s-1

        if (s + 2 < NSTAGE) {  // refill buffer (s+2)%3 == (s-1)%3, now free
            issue(s + 2, (s + 2) % 3);
            cp_commit();
        }

        const uint32_t tbase = sbase + (uint32_t)buf * GT_BUF;
#pragma unroll
        for (int kk2 = 0; kk2 < 2; kk2++) {
            uint32_t ah[4][4], al[4][4], bh[2][4], bl[2][4];
#pragma unroll
            for (int mi = 0; mi < 4; mi++) {
                ldsm4(ah[mi], tbase + offA[kk2][mi]);
                ldsm4(al[mi], tbase + GT_TILE + offA[kk2][mi]);
            }
#pragma unroll
            for (int nb = 0; nb < 2; nb++) {
                ldsm4(bh[nb], tbase + 2 * GT_TILE + offB[kk2][nb]);
                ldsm4(bl[nb], tbase + 3 * GT_TILE + offB[kk2][nb]);
            }
#pragma unroll
            for (int mi = 0; mi < 4; mi++) {
#pragma unroll
                for (int ni = 0; ni < 4; ni++) {
                    const int nb = ni >> 1;
                    const int nsub = ni & 1;
                    uint32_t bh0 = bh[nb][nsub], bh1 = bh[nb][nsub + 2];
                    uint32_t bl0 = bl[nb][nsub], bl1 = bl[nb][nsub + 2];
                    mma16816(acc[mi][ni], ah[mi], bh0, bh1);
                    mma16816(acc[mi][ni], ah[mi], bl0, bl1);
                    mma16816(acc[mi][ni], al[mi], bh0, bh1);
                }
            }
        }
        buf = (buf + 1) % 3;
    }

    // epilogue
    const int erow = lane >> 2;
    const int ecol = (lane & 3) << 1;
#pragma unroll
    for (int mi = 0; mi < 4; mi++) {
#pragma unroll
        for (int ni = 0; ni < 4; ni++) {
            int r = block_row + wm * 64 + mi * 16 + erow;
            int col = block_col + wn * 32 + ni * 8 + ecol;
            float2 bv = *(const float2*)(bias + col);
            if (r < M) {
                float2 o = make_float2(acc[mi][ni][0] + bv.x,
                                       acc[mi][ni][1] + bv.y);
                *(float2*)(C + (size_t)r * N + col) = o;
            }
            if (r + 8 < M) {
                float2 o = make_float2(acc[mi][ni][2] + bv.x,
                                       acc[mi][ni][3] + bv.y);
                *(float2*)(C + (size_t)(r + 8) * N + col) = o;
            }
        }
    }
}

// ====== RoPE + split (B,N,3,H,D) -> Q/K/V (B*H, N, D) bf16 hi/lo ===========
__global__ __launch_bounds__(256) void k_rope_split(const float* __restrict__ cosb,
                                                    const float* __restrict__ sinb) {
    int idx = blockIdx.x * blockDim.x + threadIdx.x;
    const int total = BATCH * HEADS * NTOK * (DHEAD / 2);
    if (idx >= total) return;

    int d2 = idx & 31;
    int n  = (idx >> 5) % NTOK;
    int h  = (idx / (32 * NTOK)) % HEADS;
    int b  = idx / (32 * NTOK * HEADS);

    size_t base = (size_t)(b * NTOK + n) * QKVCOLS + h * DHEAD + (d2 << 1);
    float2 q = *(const float2*)(g_qkv + base);
    float2 k = *(const float2*)(g_qkv + base + CDIM);
    float2 v = *(const float2*)(g_qkv + base + 2 * CDIM);

    if (n > 0) {
        float c = cosb[(size_t)(n - 1) * 32 + d2];
        float s = sinb[(size_t)(n - 1) * 32 + d2];
        float2 qr, kr;
        qr.x = q.x * c - q.y * s;  qr.y = q.x * s + q.y * c;
        kr.x = k.x * c - k.y * s;  kr.y = k.x * s + k.y * c;
        q = qr; k = kr;
    }

    size_t o = ((size_t)(b * HEADS + h) * NTOK + n) * DHEAD + (d2 << 1);

    float qhx = __bfloat162float(__float2bfloat16_rn(q.x));
    float qhy = __bfloat162float(__float2bfloat16_rn(q.y));
    float khx = __bfloat162float(__float2bfloat16_rn(k.x));
    float khy = __bfloat162float(__float2bfloat16_rn(k.y));
    float vhx = __bfloat162float(__float2bfloat16_rn(v.x));
    float vhy = __bfloat162float(__float2bfloat16_rn(v.y));

    *(uint32_t*)(gQh + o) = pack_bf16x2(qhx, qhy);
    *(uint32_t*)(gQl + o) = pack_bf16x2(q.x - qhx, q.y - qhy);
    *(uint32_t*)(gKh + o) = pack_bf16x2(khx, khy);
    *(uint32_t*)(gKl + o) = pack_bf16x2(k.x - khx, k.y - khy);
    *(uint32_t*)(gVh + o) = pack_bf16x2(vhx, vhy);
    *(uint32_t*)(gVl + o) = pack_bf16x2(v.x - vhx, v.y - vhy);
}

// ============== Flash attention on HMMA, bf16x3, 128 q-rows/CTA =============
#define ASM_QH 0
#define ASM_QL 16384
#define ASM_KH 32768
#define ASM_KL 40960
#define ASM_VH 49152
#define ASM_VL 57344
#define ASM_TOTAL 65536

__global__ __launch_bounds__(256) void k_attn_mma() {
    extern __shared__ __align__(128) char asmem[];
    const uint32_t sb = smem_to_u32(asmem);
    const int tid = threadIdx.x;
    const int lane = tid & 31;
    const int wid = tid >> 5;
    const int bh = blockIdx.y;
    const int q0 = blockIdx.x * 128;
    const size_t gbase = (size_t)bh * NTOK * DHEAD;

#pragma unroll
    for (int i = 0; i < 4; i++) {
        int u = tid + (i << 8);
        int r = u >> 3, c = u & 7;
        uint32_t so = (uint32_t)(r * 128 + ((c ^ (r & 7)) << 4));
        uint4 zh = make_uint4(0, 0, 0, 0), zl = zh;
        if (q0 + r < NTOK) {
            size_t g = gbase + (size_t)(q0 + r) * DHEAD + c * 8;
            zh = *(const uint4*)(gQh + g);
            zl = *(const uint4*)(gQl + g);
        }
        *(uint4*)(asmem + ASM_QH + so) = zh;
        *(uint4*)(asmem + ASM_QL + so) = zl;
    }

    const int m0 = wid * 16;
    const int alr = m0 + (lane & 15);
    const int akc = lane >> 4;
    uint32_t offQ[4];
#pragma unroll
    for (int k16 = 0; k16 < 4; k16++)
        offQ[k16] = (uint32_t)(alr * 128 + (((2 * k16 + akc) ^ (alr & 7)) << 4));

    float m_[2] = {-1e30f, -1e30f};
    float l_[2] = {0.f, 0.f};
    float o[8][4];
#pragma unroll
    for (int t = 0; t < 8; t++)
#pragma unroll
        for (int j = 0; j < 4; j++) o[t][j] = 0.f;

    const float scale = 0.125f;

    for (int kt = 0; kt < 10; kt++) {
        const int k0 = kt * 64;
        __syncthreads();

#pragma unroll
        for (int i = 0; i < 2; i++) {
            int u = tid + (i << 8);
            int r = u >> 3, c = u & 7;
            uint32_t so = (uint32_t)(r * 128 + ((c ^ (r & 7)) << 4));
            uint4 kh = make_uint4(0, 0, 0, 0), kl = kh, vh = kh, vl = kh;
            if (k0 + r < NTOK) {
                size_t g = gbase + (size_t)(k0 + r) * DHEAD + c * 8;
                kh = *(const uint4*)(gKh + g);
                kl = *(const uint4*)(gKl + g);
                vh = *(const uint4*)(gVh + g);
                vl = *(const uint4*)(gVl + g);
            }
            *(uint4*)(asmem + ASM_KH + so) = kh;
            *(uint4*)(asmem + ASM_KL + so) = kl;
            *(uint4*)(asmem + ASM_VH + so) = vh;
            *(uint4*)(asmem + ASM_VL + so) = vl;
        }
        __syncthreads();

        float s[8][4];
#pragma unroll
        for (int t = 0; t < 8; t++)
#pragma unroll
            for (int j = 0; j < 4; j++) s[t][j] = 0.f;

#pragma unroll
        for (int k16 = 0; k16 < 4; k16++) {
            uint32_t qh[4], ql[4];
            ldsm4(qh, sb + ASM_QH + offQ[k16]);
            ldsm4(ql, sb + ASM_QL + offQ[k16]);
            uint32_t kh[4][4], kl[4][4];
#pragma unroll
            for (int nb = 0; nb < 4; nb++) {
                int krow = nb * 16 + (lane & 15);
                uint32_t off = (uint32_t)(krow * 128 +
                                (((2 * k16 + akc) ^ (krow & 7)) << 4));
                ldsm4(kh[nb], sb + ASM_KH + off);
                ldsm4(kl[nb], sb + ASM_KL + off);
            }
#pragma unroll
            for (int nb = 0; nb < 4; nb++) {
#pragma unroll
                for (int nsub = 0; nsub < 2; nsub++) {
                    int t = nb * 2 + nsub;
                    uint32_t bh0 = kh[nb][nsub], bh1 = kh[nb][nsub + 2];
                    uint32_t bl0 = kl[nb][nsub], bl1 = kl[nb][nsub + 2];
                    mma16816(s[t], qh, bh0, bh1);
                    mma16816(s[t], qh, bl0, bl1);
                    mma16816(s[t], ql, bh0, bh1);
                }
            }
        }

        const bool lastt = (k0 + 64 > NTOK);
        float fi[2];
#pragma unroll
        for (int j = 0; j < 2; j++) {
            float rm = -1e30f;
#pragma unroll
            for (int t = 0; t < 8; t++) {
#pragma unroll
                for (int c = 0; c < 2; c++) {
                    float v = s[t][j * 2 + c] * scale;
                    if (lastt) {
                        int col = k0 + t * 8 + ((lane & 3) << 1) + c;
                        if (col >= NTOK) v = -1e30f;
                    }
                    s[t][j * 2 + c] = v;
                    rm = fmaxf(rm, v);
                }
            }
            rm = fmaxf(rm, __shfl_xor_sync(0xffffffffu, rm, 1));
            rm = fmaxf(rm, __shfl_xor_sync(0xffffffffu, rm, 2));
            float mn = fmaxf(m_[j], rm);
            fi[j] = __expf(m_[j] - mn);
            m_[j] = mn;
            float rs = 0.f;
#pragma unroll
            for (int t = 0; t < 8; t++) {
#pragma unroll
                for (int c = 0; c < 2; c++) {
                    float p = __expf(s[t][j * 2 + c] - mn);
                    s[t][j * 2 + c] = p;
                    rs += p;
                }
            }
            rs += __shfl_xor_sync(0xffffffffu, rs, 1);
            rs += __shfl_xor_sync(0xffffffffu, rs, 2);
            l_[j] = l_[j] * fi[j] + rs;
        }
#pragma unroll
        for (int t = 0; t < 8; t++) {
            o[t][0] *= fi[0]; o[t][1] *= fi[0];
            o[t][2] *= fi[1]; o[t][3] *= fi[1];
        }

#pragma unroll
        for (int t2 = 0; t2 < 4; t2++) {
            uint32_t ph[4], pl[4];
#pragma unroll
            for (int idx = 0; idx < 4; idx++) {
                int t = 2 * t2 + (idx >> 1);
                int j = idx & 1;
                float x0 = s[t][j * 2 + 0];
                float x1 = s[t][j * 2 + 1];
                float h0 = __bfloat162float(__float2bfloat16_rn(x0));
                float h1 = __bfloat162float(__float2bfloat16_rn(x1));
                ph[idx] = pack_bf16x2(h0, h1);
                pl[idx] = pack_bf16x2(x0 - h0, x1 - h1);
            }
            const int vm = lane >> 3;
            const int vk = t2 * 16 + ((vm & 1) << 3) + (lane & 7);
#pragma unroll
            for (int nb = 0; nb < 4; nb++) {
                int vc = nb * 2 + (vm >> 1);
                uint32_t off = (uint32_t)(vk * 128 + ((vc ^ (vk & 7)) << 4));
                uint32_t vh[4], vl[4];
                ldsm4t(vh, sb + ASM_VH + off);
                ldsm4t(vl, sb + ASM_VL + off);
                mma16816(o[nb * 2 + 0], ph, vh[0], vh[1]);
                mma16816(o[nb * 2 + 0], ph, vl[0], vl[1]);
                mma16816(o[nb * 2 + 0], pl, vh[0], vh[1]);
                mma16816(o[nb * 2 + 1], ph, vh[2], vh[3]);
                mma16816(o[nb * 2 + 1], ph, vl[2], vl[3]);
                mma16816(o[nb * 2 + 1], pl, vh[2], vh[3]);
            }
        }
    }

    const int b = bh / HEADS;
    const int h = bh % HEADS;
#pragma unroll
    for (int j = 0; j < 2; j++) {
        int n = q0 + m0 + (lane >> 2) + j * 8;
        if (n < NTOK) {
            float inv = 1.f / l_[j];
            size_t gr = (size_t)(b * NTOK + n) * CDIM + h * DHEAD;
#pragma unroll
            for (int t = 0; t < 8; t++) {
                int col = t * 8 + ((lane & 3) << 1);
                float x0 = o[t][j * 2 + 0] * inv;
                float x1 = o[t][j * 2 + 1] * inv;
                float h0 = __bfloat162float(__float2bfloat16_rn(x0));
                float h1 = __bfloat162float(__float2bfloat16_rn(x1));
                *(uint32_t*)(gCh + gr + col) = pack_bf16x2(h0, h1);
                *(uint32_t*)(gCl + gr + col) = pack_bf16x2(x0 - h0, x1 - h1);
            }
        }
    }
}

// ================================ launch ====================================
extern "C" void kernel_launch(void* const* d_in, const int* in_sizes, int n_in,
                              void* d_out, int out_size) {
    const float* x      = (const float*)d_in[0];
    const float* cosb   = (const float*)d_in[1];
    const float* sinb   = (const float*)d_in[2];
    const float* w_qkv  = (const float*)d_in[3];
    const float* b_qkv  = (const float*)d_in[4];
    const float* w_proj = (const float*)d_in[5];
    const float* b_proj = (const float*)d_in[6];
    float* out = (float*)d_out;

    cudaFuncSetAttribute(k_gemm_mma, cudaFuncAttributeMaxDynamicSharedMemorySize,
                         GT_SMEM);
    cudaFuncSetAttribute(k_attn_mma, cudaFuncAttributeMaxDynamicSharedMemorySize,
                         ASM_TOTAL);

    __nv_bfloat16 *pAh, *pAl, *pCh, *pCl, *pWqh, *pWql, *pWph, *pWpl;
    cudaGetSymbolAddress((void**)&pAh,  gAh);
    cudaGetSymbolAddress((void**)&pAl,  gAl);
    cudaGetSymbolAddress((void**)&pCh,  gCh);
    cudaGetSymbolAddress((void**)&pCl,  gCl);
    cudaGetSymbolAddress((void**)&pWqh, gWqh);
    cudaGetSymbolAddress((void**)&pWql, gWql);
    cudaGetSymbolAddress((void**)&pWph, gWph);
    cudaGetSymbolAddress((void**)&pWpl, gWpl);
    float* pqkv;
    cudaGetSymbolAddress((void**)&pqkv, g_qkv);

    const int n4 = MROWS * CDIM / 4;

    // 0) operand preparation
    k_split4<<<(n4 + 255) / 256, 256>>>(x, pAh, pAl, n4);
    {
        dim3 g(QKVCOLS / 32, CDIM / 32), b(32, 8);
        k_wsplit_t<<<g, b>>>(w_qkv, pWqh, pWql, CDIM, QKVCOLS);
    }
    {
        dim3 g(CDIM / 32, CDIM / 32), b(32, 8);
        k_wsplit_t<<<g, b>>>(w_proj, pWph, pWpl, CDIM, CDIM);
    }

    // 1) QKV GEMM (HMMA bf16x3, cp.async pipeline)
    {
        dim3 grid(QKVCOLS / 128, (MROWS + 127) / 128);
        k_gemm_mma<<<grid, 256, GT_SMEM>>>(pAh, pAl, pWqh, pWql, b_qkv, pqkv,
                                           MROWS, QKVCOLS);
    }
    // 2) RoPE + split to bf16 hi/lo Q/K/V
    {
        int total = BATCH * HEADS * NTOK * (DHEAD / 2);
        k_rope_split<<<(total + 255) / 256, 256>>>(cosb, sinb);
    }
    // 3) attention (HMMA bf16x3) — writes gCh/gCl directly
    {
        dim3 grid((NTOK + 127) / 128, BHTOT);
        k_attn_mma<<<grid, 256, ASM_TOTAL>>>();
    }
    // 4) output projection (HMMA bf16x3, cp.async pipeline)
    {
        dim3 grid(CDIM / 128, (MROWS + 127) / 128);
        k_gemm_mma<<<grid, 256, GT_SMEM>>>(pCh, pCl, pWph, pWpl, b_proj, out,
                                           MROWS, CDIM);
    }
}

// round 12
// speedup vs baseline: 3.2606x; 1.0237x over previous
#include <cuda_runtime.h>
#include <cuda_bf16.h>
#include <cstdint>
#include <cstddef>

// Problem constants
#define BATCH   16
#define NTOK    577
#define CDIM    768
#define HEADS   12
#define DHEAD   64
#define MROWS   (BATCH * NTOK)          // 9232
#define QKVCOLS (3 * CDIM)              // 2304
#define BHTOT   (BATCH * HEADS)         // 192

// ===================== helpers ==============================================
__device__ __forceinline__ uint32_t smem_to_u32(const void* smem_ptr) {
    uint32_t addr;
    asm("{ .reg .u64 tmp; cvta.to.shared.u64 tmp, %1; cvt.u32.u64 %0, tmp; }"
        : "=r"(addr) : "l"(smem_ptr));
    return addr;
}

__device__ __forceinline__ void ldsm4(uint32_t* r, uint32_t addr) {
    asm volatile("ldmatrix.sync.aligned.m8n8.x4.shared.b16 {%0,%1,%2,%3}, [%4];"
                 : "=r"(r[0]), "=r"(r[1]), "=r"(r[2]), "=r"(r[3]) : "r"(addr));
}

__device__ __forceinline__ void ldsm4t(uint32_t* r, uint32_t addr) {
    asm volatile("ldmatrix.sync.aligned.m8n8.x4.trans.shared.b16 {%0,%1,%2,%3}, [%4];"
                 : "=r"(r[0]), "=r"(r[1]), "=r"(r[2]), "=r"(r[3]) : "r"(addr));
}

__device__ __forceinline__ void mma16816(float* c, const uint32_t* a,
                                         uint32_t b0, uint32_t b1) {
    asm volatile(
        "mma.sync.aligned.m16n8k16.row.col.f32.bf16.bf16.f32 "
        "{%0,%1,%2,%3}, {%4,%5,%6,%7}, {%8,%9}, {%0,%1,%2,%3};"
        : "+f"(c[0]), "+f"(c[1]), "+f"(c[2]), "+f"(c[3])
        : "r"(a[0]), "r"(a[1]), "r"(a[2]), "r"(a[3]), "r"(b0), "r"(b1));
}

// pack(lo, hi) -> bf16x2 register
__device__ __forceinline__ uint32_t pack_bf16x2(float lo, float hi) {
    uint32_t r;
    asm("cvt.rn.bf16x2.f32 %0, %1, %2;" : "=r"(r) : "f"(hi), "f"(lo));
    return r;
}

// 16B async copy; pred=false => zero-fill (reads 0 bytes)
__device__ __forceinline__ void cp_async16(uint32_t dst, const void* src, bool pred) {
    int sz = pred ? 16 : 0;
    asm volatile("cp.async.cg.shared.global [%0], [%1], 16, %2;"
                 :: "r"(dst), "l"(src), "r"(sz) : "memory");
}
__device__ __forceinline__ void cp_commit() {
    asm volatile("cp.async.commit_group;" ::: "memory");
}
template <int N>
__device__ __forceinline__ void cp_wait() {
    asm volatile("cp.async.wait_group %0;" :: "n"(N) : "memory");
}

// ---------------- scratch (no allocations allowed -> device globals) --------
__device__ float g_qkv[(size_t)MROWS * QKVCOLS];              // (B*N, 3C)

// bf16 hi/lo split operands for tensor-core GEMMs
__device__ __nv_bfloat16 gAh[(size_t)MROWS * CDIM];           // x split
__device__ __nv_bfloat16 gAl[(size_t)MROWS * CDIM];
__device__ __nv_bfloat16 gCh[(size_t)MROWS * CDIM];           // attn-out split
__device__ __nv_bfloat16 gCl[(size_t)MROWS * CDIM];
__device__ __nv_bfloat16 gWqh[(size_t)QKVCOLS * CDIM];        // w_qkv^T split
__device__ __nv_bfloat16 gWql[(size_t)QKVCOLS * CDIM];
__device__ __nv_bfloat16 gWph[(size_t)CDIM * CDIM];           // w_proj^T split
__device__ __nv_bfloat16 gWpl[(size_t)CDIM * CDIM];

// bf16 hi/lo Q/K/V, (B*H, N, D)
__device__ __nv_bfloat16 gQh[(size_t)BHTOT * NTOK * DHEAD];
__device__ __nv_bfloat16 gQl[(size_t)BHTOT * NTOK * DHEAD];
__device__ __nv_bfloat16 gKh[(size_t)BHTOT * NTOK * DHEAD];
__device__ __nv_bfloat16 gKl[(size_t)BHTOT * NTOK * DHEAD];
__device__ __nv_bfloat16 gVh[(size_t)BHTOT * NTOK * DHEAD];
__device__ __nv_bfloat16 gVl[(size_t)BHTOT * NTOK * DHEAD];

// =============== fused operand prep (split x + transpose/split weights) =====
#define NB_X  ((MROWS * CDIM / 4 + 255) / 256)           // 6924
#define NB_WQ ((QKVCOLS / 32) * (CDIM / 32))             // 1728
#define NB_WP ((CDIM / 32) * (CDIM / 32))                // 576

__device__ __forceinline__ void wsplit_body(const float* __restrict__ w,
                                            __nv_bfloat16* __restrict__ oh,
                                            __nv_bfloat16* __restrict__ ol,
                                            int K, int N, int bx, int by,
                                            int tid, float (*t)[33]) {
    int n0 = bx * 32, k0 = by * 32;
    int tx = tid & 31, ty = tid >> 5;
#pragma unroll
    for (int j = 0; j < 32; j += 8)
        t[ty + j][tx] = w[(size_t)(k0 + ty + j) * N + n0 + tx];
    __syncthreads();
#pragma unroll
    for (int j = 0; j < 32; j += 8) {
        float v = t[tx][ty + j];
        int n = n0 + ty + j, k = k0 + tx;
        __nv_bfloat16 h = __float2bfloat16_rn(v);
        __nv_bfloat16 l = __float2bfloat16_rn(v - __bfloat162float(h));
        oh[(size_t)n * K + k] = h;
        ol[(size_t)n * K + k] = l;
    }
}

__global__ __launch_bounds__(256) void k_prep(const float* __restrict__ x,
                                              const float* __restrict__ w_qkv,
                                              const float* __restrict__ w_proj) {
    __shared__ float t[32][33];
    const int b = blockIdx.x;
    const int tid = threadIdx.x;
    if (b < NB_X) {
        int i = b * 256 + tid;
        const int n4 = MROWS * CDIM / 4;
        if (i < n4) {
            float4 v = ((const float4*)x)[i];
            float f[4] = {v.x, v.y, v.z, v.w};
            __align__(8) __nv_bfloat16 h[4];
            __align__(8) __nv_bfloat16 l[4];
#pragma unroll
            for (int j = 0; j < 4; j++) {
                h[j] = __float2bfloat16_rn(f[j]);
                l[j] = __float2bfloat16_rn(f[j] - __bfloat162float(h[j]));
            }
            *(uint2*)(gAh + 4 * (size_t)i) = *(uint2*)h;
            *(uint2*)(gAl + 4 * (size_t)i) = *(uint2*)l;
        }
    } else if (b < NB_X + NB_WQ) {
        int bb = b - NB_X;
        wsplit_body(w_qkv, gWqh, gWql, CDIM, QKVCOLS,
                    bb % (QKVCOLS / 32), bb / (QKVCOLS / 32), tid, t);
    } else {
        int bb = b - NB_X - NB_WQ;
        wsplit_body(w_proj, gWph, gWpl, CDIM, CDIM,
                    bb % (CDIM / 32), bb / (CDIM / 32), tid, t);
    }
}

// =================== HMMA bf16x3 GEMM: C = A@B + bias =======================
// 3-stage cp.async pipeline; 2 CTAs/SM. Tile 128x128, BK=32, 8 warps (2x4).
#define GT_TILE 8192                    // 128 x 32 bf16
#define GT_BUF  (4 * GT_TILE)           // 32KB / stage (Ah,Al,Bh,Bl)
#define GT_SMEM (3 * GT_BUF)            // 96KB, 3 stages

__global__ __launch_bounds__(256, 2) void k_gemm_mma(
    const __nv_bfloat16* __restrict__ Ah, const __nv_bfloat16* __restrict__ Al,
    const __nv_bfloat16* __restrict__ Bh, const __nv_bfloat16* __restrict__ Bl,
    const float* __restrict__ bias, float* __restrict__ C, int M, int N) {
    extern __shared__ __align__(128) char smem[];
    const uint32_t sbase = smem_to_u32(smem);

    const int tid  = threadIdx.x;
    const int lane = tid & 31;
    const int wid  = tid >> 5;
    const int wm   = wid >> 2;
    const int wn   = wid & 3;
    const int block_row = blockIdx.y * 128;
    const int block_col = blockIdx.x * 128;

    // global->smem chunk mapping (2 chunks per thread per tile)
    const int u0 = tid, u1 = tid + 256;
    const int r0 = u0 >> 2, c0 = u0 & 3;
    const int r1 = u1 >> 2, c1 = u1 & 3;
    const uint32_t so0 = (uint32_t)(r0 * 64 + ((c0 ^ ((r0 >> 1) & 3)) << 4));
    const uint32_t so1 = (uint32_t)(r1 * 64 + ((c1 ^ ((r1 >> 1) & 3)) << 4));
    const bool a0ok = (block_row + r0) < M;
    const bool a1ok = (block_row + r1) < M;
    const int ar0 = a0ok ? (block_row + r0) : (M - 1);
    const int ar1 = a1ok ? (block_row + r1) : (M - 1);
    const size_t gA0 = (size_t)ar0 * CDIM + c0 * 8;
    const size_t gA1 = (size_t)ar1 * CDIM + c1 * 8;
    const size_t gB0 = (size_t)(block_col + r0) * CDIM + c0 * 8;
    const size_t gB1 = (size_t)(block_col + r1) * CDIM + c1 * 8;

    // ldmatrix source offsets (loop invariant)
    const int lrow = lane & 15;
    const int lkc  = lane >> 4;
    uint32_t offA[2][4], offB[2][2];
#pragma unroll
    for (int kk2 = 0; kk2 < 2; kk2++) {
        int cc = kk2 * 2 + lkc;
#pragma unroll
        for (int mi = 0; mi < 4; mi++) {
            int rr = wm * 64 + mi * 16 + lrow;
            offA[kk2][mi] = (uint32_t)(rr * 64 + ((cc ^ ((rr >> 1) & 3)) << 4));
        }
#pragma unroll
        for (int nb = 0; nb < 2; nb++) {
            int rr = wn * 32 + nb * 16 + lrow;
            offB[kk2][nb] = (uint32_t)(rr * 64 + ((cc ^ ((rr >> 1) & 3)) << 4));
        }
    }

    float acc[4][4][4];
#pragma unroll
    for (int mi = 0; mi < 4; mi++)
#pragma unroll
        for (int ni = 0; ni < 4; ni++)
#pragma unroll
            for (int j = 0; j < 4; j++) acc[mi][ni][j] = 0.f;

    const int NSTAGE = CDIM / 32;        // 24

    auto issue = [&](int s, int buf) {
        const int ko = s * 32;
        const uint32_t b = sbase + (uint32_t)buf * GT_BUF;
        cp_async16(b + so0,               Ah + gA0 + ko, a0ok);
        cp_async16(b + so1,               Ah + gA1 + ko, a1ok);
        cp_async16(b + GT_TILE + so0,     Al + gA0 + ko, a0ok);
        cp_async16(b + GT_TILE + so1,     Al + gA1 + ko, a1ok);
        cp_async16(b + 2 * GT_TILE + so0, Bh + gB0 + ko, true);
        cp_async16(b + 2 * GT_TILE + so1, Bh + gB1 + ko, true);
        cp_async16(b + 3 * GT_TILE + so0, Bl + gB0 + ko, true);
        cp_async16(b + 3 * GT_TILE + so1, Bl + gB1 + ko, true);
    };

    issue(0, 0); cp_commit();
    issue(1, 1); cp_commit();

    int buf = 0;
    for (int s = 0; s < NSTAGE; s++) {
        cp_wait<1>();
        __syncthreads();

        if (s + 2 < NSTAGE) {
            issue(s + 2, (s + 2) % 3);
            cp_commit();
        }

        const uint32_t tbase = sbase + (uint32_t)buf * GT_BUF;
#pragma unroll
        for (int kk2 = 0; kk2 < 2; kk2++) {
            uint32_t ah[4][4], al[4][4];
#pragma unroll
            for (int mi = 0; mi < 4; mi++) {
                ldsm4(ah[mi], tbase + offA[kk2][mi]);
                ldsm4(al[mi], tbase + GT_TILE + offA[kk2][mi]);
            }
#pragma unroll
            for (int nb = 0; nb < 2; nb++) {
                uint32_t bh[4], bl[4];
                ldsm4(bh, tbase + 2 * GT_TILE + offB[kk2][nb]);
                ldsm4(bl, tbase + 3 * GT_TILE + offB[kk2][nb]);
#pragma unroll
                for (int mi = 0; mi < 4; mi++) {
#pragma unroll
                    for (int nsub = 0; nsub < 2; nsub++) {
                        const int ni = nb * 2 + nsub;
                        uint32_t b0 = bh[nsub], b1 = bh[nsub + 2];
                        uint32_t c0r = bl[nsub], c1r = bl[nsub + 2];
                        mma16816(acc[mi][ni], ah[mi], b0, b1);
                        mma16816(acc[mi][ni], ah[mi], c0r, c1r);
                        mma16816(acc[mi][ni], al[mi], b0, b1);
                    }
                }
            }
        }
        buf = (buf + 1) % 3;
    }

    // epilogue
    const int erow = lane >> 2;
    const int ecol = (lane & 3) << 1;
#pragma unroll
    for (int mi = 0; mi < 4; mi++) {
#pragma unroll
        for (int ni = 0; ni < 4; ni++) {
            int r = block_row + wm * 64 + mi * 16 + erow;
            int col = block_col + wn * 32 + ni * 8 + ecol;
            float2 bv = *(const float2*)(bias + col);
            if (r < M) {
                float2 o = make_float2(acc[mi][ni][0] + bv.x,
                                       acc[mi][ni][1] + bv.y);
                *(float2*)(C + (size_t)r * N + col) = o;
            }
            if (r + 8 < M) {
                float2 o = make_float2(acc[mi][ni][2] + bv.x,
                                       acc[mi][ni][3] + bv.y);
                *(float2*)(C + (size_t)(r + 8) * N + col) = o;
            }
        }
    }
}

// ====== RoPE + split (B,N,3,H,D) -> Q/K/V (B*H, N, D) bf16 hi/lo ===========
__global__ __launch_bounds__(256) void k_rope_split(const float* __restrict__ cosb,
                                                    const float* __restrict__ sinb) {
    int idx = blockIdx.x * blockDim.x + threadIdx.x;
    const int total = BATCH * HEADS * NTOK * (DHEAD / 2);
    if (idx >= total) return;

    int d2 = idx & 31;
    int n  = (idx >> 5) % NTOK;
    int h  = (idx / (32 * NTOK)) % HEADS;
    int b  = idx / (32 * NTOK * HEADS);

    size_t base = (size_t)(b * NTOK + n) * QKVCOLS + h * DHEAD + (d2 << 1);
    float2 q = *(const float2*)(g_qkv + base);
    float2 k = *(const float2*)(g_qkv + base + CDIM);
    float2 v = *(const float2*)(g_qkv + base + 2 * CDIM);

    if (n > 0) {
        float c = cosb[(size_t)(n - 1) * 32 + d2];
        float s = sinb[(size_t)(n - 1) * 32 + d2];
        float2 qr, kr;
        qr.x = q.x * c - q.y * s;  qr.y = q.x * s + q.y * c;
        kr.x = k.x * c - k.y * s;  kr.y = k.x * s + k.y * c;
        q = qr; k = kr;
    }

    size_t o = ((size_t)(b * HEADS + h) * NTOK + n) * DHEAD + (d2 << 1);

    float qhx = __bfloat162float(__float2bfloat16_rn(q.x));
    float qhy = __bfloat162float(__float2bfloat16_rn(q.y));
    float khx = __bfloat162float(__float2bfloat16_rn(k.x));
    float khy = __bfloat162float(__float2bfloat16_rn(k.y));
    float vhx = __bfloat162float(__float2bfloat16_rn(v.x));
    float vhy = __bfloat162float(__float2bfloat16_rn(v.y));

    *(uint32_t*)(gQh + o) = pack_bf16x2(qhx, qhy);
    *(uint32_t*)(gQl + o) = pack_bf16x2(q.x - qhx, q.y - qhy);
    *(uint32_t*)(gKh + o) = pack_bf16x2(khx, khy);
    *(uint32_t*)(gKl + o) = pack_bf16x2(k.x - khx, k.y - khy);
    *(uint32_t*)(gVh + o) = pack_bf16x2(vhx, vhy);
    *(uint32_t*)(gVl + o) = pack_bf16x2(v.x - vhx, v.y - vhy);
}

// ============== Flash attention on HMMA, bf16x3, 128 q-rows/CTA =============
#define ASM_QH 0
#define ASM_QL 16384
#define ASM_KH 32768
#define ASM_KL 40960
#define ASM_VH 49152
#define ASM_VL 57344
#define ASM_TOTAL 65536

__global__ __launch_bounds__(256, 2) void k_attn_mma() {
    extern __shared__ __align__(128) char asmem[];
    const uint32_t sb = smem_to_u32(asmem);
    const int tid = threadIdx.x;
    const int lane = tid & 31;
    const int wid = tid >> 5;
    const int bh = blockIdx.y;
    const int q0 = blockIdx.x * 128;
    const size_t gbase = (size_t)bh * NTOK * DHEAD;

#pragma unroll
    for (int i = 0; i < 4; i++) {
        int u = tid + (i << 8);
        int r = u >> 3, c = u & 7;
        uint32_t so = (uint32_t)(r * 128 + ((c ^ (r & 7)) << 4));
        uint4 zh = make_uint4(0, 0, 0, 0), zl = zh;
        if (q0 + r < NTOK) {
            size_t g = gbase + (size_t)(q0 + r) * DHEAD + c * 8;
            zh = *(const uint4*)(gQh + g);
            zl = *(const uint4*)(gQl + g);
        }
        *(uint4*)(asmem + ASM_QH + so) = zh;
        *(uint4*)(asmem + ASM_QL + so) = zl;
    }

    const int m0 = wid * 16;
    const int alr = m0 + (lane & 15);
    const int akc = lane >> 4;
    uint32_t offQ[4];
#pragma unroll
    for (int k16 = 0; k16 < 4; k16++)
        offQ[k16] = (uint32_t)(alr * 128 + (((2 * k16 + akc) ^ (alr & 7)) << 4));

    float m_[2] = {-1e30f, -1e30f};
    float l_[2] = {0.f, 0.f};
    float o[8][4];
#pragma unroll
    for (int t = 0; t < 8; t++)
#pragma unroll
        for (int j = 0; j < 4; j++) o[t][j] = 0.f;

    const float scale = 0.125f;

    for (int kt = 0; kt < 10; kt++) {
        const int k0 = kt * 64;
        __syncthreads();

#pragma unroll
        for (int i = 0; i < 2; i++) {
            int u = tid + (i << 8);
            int r = u >> 3, c = u & 7;
            uint32_t so = (uint32_t)(r * 128 + ((c ^ (r & 7)) << 4));
            uint4 kh = make_uint4(0, 0, 0, 0), kl = kh, vh = kh, vl = kh;
            if (k0 + r < NTOK) {
                size_t g = gbase + (size_t)(k0 + r) * DHEAD + c * 8;
                kh = *(const uint4*)(gKh + g);
                kl = *(const uint4*)(gKl + g);
                vh = *(const uint4*)(gVh + g);
                vl = *(const uint4*)(gVl + g);
            }
            *(uint4*)(asmem + ASM_KH + so) = kh;
            *(uint4*)(asmem + ASM_KL + so) = kl;
            *(uint4*)(asmem + ASM_VH + so) = vh;
            *(uint4*)(asmem + ASM_VL + so) = vl;
        }
        __syncthreads();

        float s[8][4];
#pragma unroll
        for (int t = 0; t < 8; t++)
#pragma unroll
            for (int j = 0; j < 4; j++) s[t][j] = 0.f;

#pragma unroll
        for (int k16 = 0; k16 < 4; k16++) {
            uint32_t qh[4], ql[4];
            ldsm4(qh, sb + ASM_QH + offQ[k16]);
            ldsm4(ql, sb + ASM_QL + offQ[k16]);
#pragma unroll
            for (int nb = 0; nb < 4; nb++) {
                int krow = nb * 16 + (lane & 15);
                uint32_t off = (uint32_t)(krow * 128 +
                                (((2 * k16 + akc) ^ (krow & 7)) << 4));
                uint32_t kh[4], kl[4];
                ldsm4(kh, sb + ASM_KH + off);
                ldsm4(kl, sb + ASM_KL + off);
#pragma unroll
                for (int nsub = 0; nsub < 2; nsub++) {
                    int t = nb * 2 + nsub;
                    uint32_t bh0 = kh[nsub], bh1 = kh[nsub + 2];
                    uint32_t bl0 = kl[nsub], bl1 = kl[nsub + 2];
                    mma16816(s[t], qh, bh0, bh1);
                    mma16816(s[t], qh, bl0, bl1);
                    mma16816(s[t], ql, bh0, bh1);
                }
            }
        }

        const bool lastt = (k0 + 64 > NTOK);
        float fi[2];
#pragma unroll
        for (int j = 0; j < 2; j++) {
            float rm = -1e30f;
#pragma unroll
            for (int t = 0; t < 8; t++) {
#pragma unroll
                for (int c = 0; c < 2; c++) {
                    float v = s[t][j * 2 + c] * scale;
                    if (lastt) {
                        int col = k0 + t * 8 + ((lane & 3) << 1) + c;
                        if (col >= NTOK) v = -1e30f;
                    }
                    s[t][j * 2 + c] = v;
                    rm = fmaxf(rm, v);
                }
            }
            rm = fmaxf(rm, __shfl_xor_sync(0xffffffffu, rm, 1));
            rm = fmaxf(rm, __shfl_xor_sync(0xffffffffu, rm, 2));
            float mn = fmaxf(m_[j], rm);
            fi[j] = __expf(m_[j] - mn);
            m_[j] = mn;
            float rs = 0.f;
#pragma unroll
            for (int t = 0; t < 8; t++) {
#pragma unroll
                for (int c = 0; c < 2; c++) {
                    float p = __expf(s[t][j * 2 + c] - mn);
                    s[t][j * 2 + c] = p;
                    rs += p;
                }
            }
            rs += __shfl_xor_sync(0xffffffffu, rs, 1);
            rs += __shfl_xor_sync(0xffffffffu, rs, 2);
            l_[j] = l_[j] * fi[j] + rs;
        }
#pragma unroll
        for (int t = 0; t < 8; t++) {
            o[t][0] *= fi[0]; o[t][1] *= fi[0];
            o[t][2] *= fi[1]; o[t][3] *= fi[1];
        }

#pragma unroll
        for (int t2 = 0; t2 < 4; t2++) {
            uint32_t ph[4], pl[4];
#pragma unroll
            for (int idx = 0; idx < 4; idx++) {
                int t = 2 * t2 + (idx >> 1);
                int j = idx & 1;
                float x0 = s[t][j * 2 + 0];
                float x1 = s[t][j * 2 + 1];
                float h0 = __bfloat162float(__float2bfloat16_rn(x0));
                float h1 = __bfloat162float(__float2bfloat16_rn(x1));
                ph[idx] = pack_bf16x2(h0, h1);
                pl[idx] = pack_bf16x2(x0 - h0, x1 - h1);
            }
            const int vm = lane >> 3;
            const int vk = t2 * 16 + ((vm & 1) << 3) + (lane & 7);
#pragma unroll
            for (int nb = 0; nb < 4; nb++) {
                int vc = nb * 2 + (vm >> 1);
                uint32_t off = (uint32_t)(vk * 128 + ((vc ^ (vk & 7)) << 4));
                uint32_t vh[4], vl[4];
                ldsm4t(vh, sb + ASM_VH + off);
                ldsm4t(vl, sb + ASM_VL + off);
                mma16816(o[nb * 2 + 0], ph, vh[0], vh[1]);
                mma16816(o[nb * 2 + 0], ph, vl[0], vl[1]);
                mma16816(o[nb * 2 + 0], pl, vh[0], vh[1]);
                mma16816(o[nb * 2 + 1], ph, vh[2], vh[3]);
                mma16816(o[nb * 2 + 1], ph, vl[2], vl[3]);
                mma16816(o[nb * 2 + 1], pl, vh[2], vh[3]);
            }
        }
    }

    const int b = bh / HEADS;
    const int h = bh % HEADS;
#pragma unroll
    for (int j = 0; j < 2; j++) {
        int n = q0 + m0 + (lane >> 2) + j * 8;
        if (n < NTOK) {
            float inv = 1.f / l_[j];
            size_t gr = (size_t)(b * NTOK + n) * CDIM + h * DHEAD;
#pragma unroll
            for (int t = 0; t < 8; t++) {
                int col = t * 8 + ((lane & 3) << 1);
                float x0 = o[t][j * 2 + 0] * inv;
                float x1 = o[t][j * 2 + 1] * inv;
                float h0 = __bfloat162float(__float2bfloat16_rn(x0));
                float h1 = __bfloat162float(__float2bfloat16_rn(x1));
                *(uint32_t*)(gCh + gr + col) = pack_bf16x2(h0, h1);
                *(uint32_t*)(gCl + gr + col) = pack_bf16x2(x0 - h0, x1 - h1);
            }
        }
    }
}

// ================================ launch ====================================
extern "C" void kernel_launch(void* const* d_in, const int* in_sizes, int n_in,
                              void* d_out, int out_size) {
    const float* x      = (const float*)d_in[0];
    const float* cosb   = (const float*)d_in[1];
    const float* sinb   = (const float*)d_in[2];
    const float* w_qkv  = (const float*)d_in[3];
    const float* b_qkv  = (const float*)d_in[4];
    const float* w_proj = (const float*)d_in[5];
    const float* b_proj = (const float*)d_in[6];
    float* out = (float*)d_out;

    cudaFuncSetAttribute(k_gemm_mma, cudaFuncAttributeMaxDynamicSharedMemorySize,
                         GT_SMEM);
    cudaFuncSetAttribute(k_attn_mma, cudaFuncAttributeMaxDynamicSharedMemorySize,
                         ASM_TOTAL);

    __nv_bfloat16 *pAh, *pAl, *pCh, *pCl, *pWqh, *pWql, *pWph, *pWpl;
    cudaGetSymbolAddress((void**)&pAh,  gAh);
    cudaGetSymbolAddress((void**)&pAl,  gAl);
    cudaGetSymbolAddress((void**)&pCh,  gCh);
    cudaGetSymbolAddress((void**)&pCl,  gCl);
    cudaGetSymbolAddress((void**)&pWqh, gWqh);
    cudaGetSymbolAddress((void**)&pWql, gWql);
    cudaGetSymbolAddress((void**)&pWph, gWph);
    cudaGetSymbolAddress((void**)&pWpl, gWpl);
    float* pqkv;
    cudaGetSymbolAddress((void**)&pqkv, g_qkv);

    // 0) fused operand preparation
    k_prep<<<NB_X + NB_WQ + NB_WP, 256>>>(x, w_qkv, w_proj);

    // 1) QKV GEMM (HMMA bf16x3, cp.async pipeline)
    {
        dim3 grid(QKVCOLS / 128, (MROWS + 127) / 128);
        k_gemm_mma<<<grid, 256, GT_SMEM>>>(pAh, pAl, pWqh, pWql, b_qkv, pqkv,
                                           MROWS, QKVCOLS);
    }
    // 2) RoPE + split to bf16 hi/lo Q/K/V
    {
        int total = BATCH * HEADS * NTOK * (DHEAD / 2);
        k_rope_split<<<(total + 255) / 256, 256>>>(cosb, sinb);
    }
    // 3) attention (HMMA bf16x3) — writes gCh/gCl directly
    {
        dim3 grid((NTOK + 127) / 128, BHTOT);
        k_attn_mma<<<grid, 256, ASM_TOTAL>>>();
    }
    // 4) output projection (HMMA bf16x3, cp.async pipeline)
    {
        dim3 grid(CDIM / 128, (MROWS + 127) / 128);
        k_gemm_mma<<<grid, 256, GT_SMEM>>>(pCh, pCl, pWph, pWpl, b_proj, out,
                                           MROWS, CDIM);
    }
}

// round 13
// speedup vs baseline: 3.4085x; 1.0454x over previous
#include <cuda_runtime.h>
#include <cuda_bf16.h>
#include <cstdint>
#include <cstddef>

// Problem constants
#define BATCH   16
#define NTOK    577
#define CDIM    768
#define HEADS   12
#define DHEAD   64
#define MROWS   (BATCH * NTOK)          // 9232
#define QKVCOLS (3 * CDIM)              // 2304
#define BHTOT   (BATCH * HEADS)         // 192

// ===================== helpers ==============================================
__device__ __forceinline__ uint32_t smem_to_u32(const void* smem_ptr) {
    uint32_t addr;
    asm("{ .reg .u64 tmp; cvta.to.shared.u64 tmp, %1; cvt.u32.u64 %0, tmp; }"
        : "=r"(addr) : "l"(smem_ptr));
    return addr;
}

__device__ __forceinline__ void ldsm4(uint32_t* r, uint32_t addr) {
    asm volatile("ldmatrix.sync.aligned.m8n8.x4.shared.b16 {%0,%1,%2,%3}, [%4];"
                 : "=r"(r[0]), "=r"(r[1]), "=r"(r[2]), "=r"(r[3]) : "r"(addr));
}

__device__ __forceinline__ void ldsm4t(uint32_t* r, uint32_t addr) {
    asm volatile("ldmatrix.sync.aligned.m8n8.x4.trans.shared.b16 {%0,%1,%2,%3}, [%4];"
                 : "=r"(r[0]), "=r"(r[1]), "=r"(r[2]), "=r"(r[3]) : "r"(addr));
}

__device__ __forceinline__ void mma16816(float* c, const uint32_t* a,
                                         uint32_t b0, uint32_t b1) {
    asm volatile(
        "mma.sync.aligned.m16n8k16.row.col.f32.bf16.bf16.f32 "
        "{%0,%1,%2,%3}, {%4,%5,%6,%7}, {%8,%9}, {%0,%1,%2,%3};"
        : "+f"(c[0]), "+f"(c[1]), "+f"(c[2]), "+f"(c[3])
        : "r"(a[0]), "r"(a[1]), "r"(a[2]), "r"(a[3]), "r"(b0), "r"(b1));
}

// pack(lo, hi) -> bf16x2 register (lo in lower 16 bits)
__device__ __forceinline__ uint32_t pack_bf16x2(float lo, float hi) {
    uint32_t r;
    asm("cvt.rn.bf16x2.f32 %0, %1, %2;" : "=r"(r) : "f"(hi), "f"(lo));
    return r;
}

// 16B async copy; pred=false => zero-fill (reads 0 bytes)
__device__ __forceinline__ void cp_async16(uint32_t dst, const void* src, bool pred) {
    int sz = pred ? 16 : 0;
    asm volatile("cp.async.cg.shared.global [%0], [%1], 16, %2;"
                 :: "r"(dst), "l"(src), "r"(sz) : "memory");
}
__device__ __forceinline__ void cp_commit() {
    asm volatile("cp.async.commit_group;" ::: "memory");
}
template <int N>
__device__ __forceinline__ void cp_wait() {
    asm volatile("cp.async.wait_group %0;" :: "n"(N) : "memory");
}

// ---------------- scratch (no allocations allowed -> device globals) --------
// bf16 hi/lo split operands for tensor-core GEMMs
__device__ __nv_bfloat16 gAh[(size_t)MROWS * CDIM];           // x split
__device__ __nv_bfloat16 gAl[(size_t)MROWS * CDIM];
__device__ __nv_bfloat16 gCh[(size_t)MROWS * CDIM];           // attn-out split
__device__ __nv_bfloat16 gCl[(size_t)MROWS * CDIM];
__device__ __nv_bfloat16 gWqh[(size_t)QKVCOLS * CDIM];        // w_qkv^T split
__device__ __nv_bfloat16 gWql[(size_t)QKVCOLS * CDIM];
__device__ __nv_bfloat16 gWph[(size_t)CDIM * CDIM];           // w_proj^T split
__device__ __nv_bfloat16 gWpl[(size_t)CDIM * CDIM];

// bf16 hi/lo Q/K/V, (B*H, N, D)
__device__ __nv_bfloat16 gQh[(size_t)BHTOT * NTOK * DHEAD];
__device__ __nv_bfloat16 gQl[(size_t)BHTOT * NTOK * DHEAD];
__device__ __nv_bfloat16 gKh[(size_t)BHTOT * NTOK * DHEAD];
__device__ __nv_bfloat16 gKl[(size_t)BHTOT * NTOK * DHEAD];
__device__ __nv_bfloat16 gVh[(size_t)BHTOT * NTOK * DHEAD];
__device__ __nv_bfloat16 gVl[(size_t)BHTOT * NTOK * DHEAD];

// =============== fused operand prep (split x + transpose/split weights) =====
#define NB_X  ((MROWS * CDIM / 4 + 255) / 256)           // 6924
#define NB_WQ ((QKVCOLS / 32) * (CDIM / 32))             // 1728
#define NB_WP ((CDIM / 32) * (CDIM / 32))                // 576

__device__ __forceinline__ void wsplit_body(const float* __restrict__ w,
                                            __nv_bfloat16* __restrict__ oh,
                                            __nv_bfloat16* __restrict__ ol,
                                            int K, int N, int bx, int by,
                                            int tid, float (*t)[33]) {
    int n0 = bx * 32, k0 = by * 32;
    int tx = tid & 31, ty = tid >> 5;
#pragma unroll
    for (int j = 0; j < 32; j += 8)
        t[ty + j][tx] = w[(size_t)(k0 + ty + j) * N + n0 + tx];
    __syncthreads();
#pragma unroll
    for (int j = 0; j < 32; j += 8) {
        float v = t[tx][ty + j];
        int n = n0 + ty + j, k = k0 + tx;
        __nv_bfloat16 h = __float2bfloat16_rn(v);
        __nv_bfloat16 l = __float2bfloat16_rn(v - __bfloat162float(h));
        oh[(size_t)n * K + k] = h;
        ol[(size_t)n * K + k] = l;
    }
}

__global__ __launch_bounds__(256) void k_prep(const float* __restrict__ x,
                                              const float* __restrict__ w_qkv,
                                              const float* __restrict__ w_proj) {
    __shared__ float t[32][33];
    const int b = blockIdx.x;
    const int tid = threadIdx.x;
    if (b < NB_X) {
        int i = b * 256 + tid;
        const int n4 = MROWS * CDIM / 4;
        if (i < n4) {
            float4 v = ((const float4*)x)[i];
            float f[4] = {v.x, v.y, v.z, v.w};
            __align__(8) __nv_bfloat16 h[4];
            __align__(8) __nv_bfloat16 l[4];
#pragma unroll
            for (int j = 0; j < 4; j++) {
                h[j] = __float2bfloat16_rn(f[j]);
                l[j] = __float2bfloat16_rn(f[j] - __bfloat162float(h[j]));
            }
            *(uint2*)(gAh + 4 * (size_t)i) = *(uint2*)h;
            *(uint2*)(gAl + 4 * (size_t)i) = *(uint2*)l;
        }
    } else if (b < NB_X + NB_WQ) {
        int bb = b - NB_X;
        wsplit_body(w_qkv, gWqh, gWql, CDIM, QKVCOLS,
                    bb % (QKVCOLS / 32), bb / (QKVCOLS / 32), tid, t);
    } else {
        int bb = b - NB_X - NB_WQ;
        wsplit_body(w_proj, gWph, gWpl, CDIM, CDIM,
                    bb % (CDIM / 32), bb / (CDIM / 32), tid, t);
    }
}

// =================== HMMA bf16x3 GEMM: C = A@B + bias =======================
// 3-stage cp.async pipeline; 2 CTAs/SM. Tile 128x128, BK=32, 8 warps (2x4).
// ROPE=true: qkv GEMM — epilogue applies RoPE + bf16 hi/lo split and scatters
// straight into gQ/gK/gV (no fp32 round-trip, no separate rope kernel).
#define GT_TILE 8192                    // 128 x 32 bf16
#define GT_BUF  (4 * GT_TILE)           // 32KB / stage (Ah,Al,Bh,Bl)
#define GT_SMEM (3 * GT_BUF)            // 96KB, 3 stages

template <bool ROPE>
__global__ __launch_bounds__(256, 2) void k_gemm_mma(
    const __nv_bfloat16* __restrict__ Ah, const __nv_bfloat16* __restrict__ Al,
    const __nv_bfloat16* __restrict__ Bh, const __nv_bfloat16* __restrict__ Bl,
    const float* __restrict__ bias, float* __restrict__ C, int M, int N,
    const float* __restrict__ cosb, const float* __restrict__ sinb) {
    extern __shared__ __align__(128) char smem[];
    const uint32_t sbase = smem_to_u32(smem);

    const int tid  = threadIdx.x;
    const int lane = tid & 31;
    const int wid  = tid >> 5;
    const int wm   = wid >> 2;
    const int wn   = wid & 3;
    const int block_row = blockIdx.y * 128;
    const int block_col = blockIdx.x * 128;

    // global->smem chunk mapping (2 chunks per thread per tile)
    const int u0 = tid, u1 = tid + 256;
    const int r0 = u0 >> 2, c0 = u0 & 3;
    const int r1 = u1 >> 2, c1 = u1 & 3;
    const uint32_t so0 = (uint32_t)(r0 * 64 + ((c0 ^ ((r0 >> 1) & 3)) << 4));
    const uint32_t so1 = (uint32_t)(r1 * 64 + ((c1 ^ ((r1 >> 1) & 3)) << 4));
    const bool a0ok = (block_row + r0) < M;
    const bool a1ok = (block_row + r1) < M;
    const int ar0 = a0ok ? (block_row + r0) : (M - 1);
    const int ar1 = a1ok ? (block_row + r1) : (M - 1);
    const size_t gA0 = (size_t)ar0 * CDIM + c0 * 8;
    const size_t gA1 = (size_t)ar1 * CDIM + c1 * 8;
    const size_t gB0 = (size_t)(block_col + r0) * CDIM + c0 * 8;
    const size_t gB1 = (size_t)(block_col + r1) * CDIM + c1 * 8;

    // ldmatrix source offsets (loop invariant)
    const int lrow = lane & 15;
    const int lkc  = lane >> 4;
    uint32_t offA[2][4], offB[2][2];
#pragma unroll
    for (int kk2 = 0; kk2 < 2; kk2++) {
        int cc = kk2 * 2 + lkc;
#pragma unroll
        for (int mi = 0; mi < 4; mi++) {
            int rr = wm * 64 + mi * 16 + lrow;
            offA[kk2][mi] = (uint32_t)(rr * 64 + ((cc ^ ((rr >> 1) & 3)) << 4));
        }
#pragma unroll
        for (int nb = 0; nb < 2; nb++) {
            int rr = wn * 32 + nb * 16 + lrow;
            offB[kk2][nb] = (uint32_t)(rr * 64 + ((cc ^ ((rr >> 1) & 3)) << 4));
        }
    }

    float acc[4][4][4];
#pragma unroll
    for (int mi = 0; mi < 4; mi++)
#pragma unroll
        for (int ni = 0; ni < 4; ni++)
#pragma unroll
            for (int j = 0; j < 4; j++) acc[mi][ni][j] = 0.f;

    const int NSTAGE = CDIM / 32;        // 24

    auto issue = [&](int s, int buf) {
        const int ko = s * 32;
        const uint32_t b = sbase + (uint32_t)buf * GT_BUF;
        cp_async16(b + so0,               Ah + gA0 + ko, a0ok);
        cp_async16(b + so1,               Ah + gA1 + ko, a1ok);
        cp_async16(b + GT_TILE + so0,     Al + gA0 + ko, a0ok);
        cp_async16(b + GT_TILE + so1,     Al + gA1 + ko, a1ok);
        cp_async16(b + 2 * GT_TILE + so0, Bh + gB0 + ko, true);
        cp_async16(b + 2 * GT_TILE + so1, Bh + gB1 + ko, true);
        cp_async16(b + 3 * GT_TILE + so0, Bl + gB0 + ko, true);
        cp_async16(b + 3 * GT_TILE + so1, Bl + gB1 + ko, true);
    };

    issue(0, 0); cp_commit();
    issue(1, 1); cp_commit();

    int buf = 0;
    for (int s = 0; s < NSTAGE; s++) {
        cp_wait<1>();
        __syncthreads();

        if (s + 2 < NSTAGE) {
            issue(s + 2, (s + 2) % 3);
            cp_commit();
        }

        const uint32_t tbase = sbase + (uint32_t)buf * GT_BUF;
#pragma unroll
        for (int kk2 = 0; kk2 < 2; kk2++) {
            uint32_t ah[4][4], al[4][4];
#pragma unroll
            for (int mi = 0; mi < 4; mi++) {
                ldsm4(ah[mi], tbase + offA[kk2][mi]);
                ldsm4(al[mi], tbase + GT_TILE + offA[kk2][mi]);
            }
#pragma unroll
            for (int nb = 0; nb < 2; nb++) {
                uint32_t bh[4], bl[4];
                ldsm4(bh, tbase + 2 * GT_TILE + offB[kk2][nb]);
                ldsm4(bl, tbase + 3 * GT_TILE + offB[kk2][nb]);
#pragma unroll
                for (int mi = 0; mi < 4; mi++) {
#pragma unroll
                    for (int nsub = 0; nsub < 2; nsub++) {
                        const int ni = nb * 2 + nsub;
                        uint32_t b0 = bh[nsub], b1 = bh[nsub + 2];
                        uint32_t c0r = bl[nsub], c1r = bl[nsub + 2];
                        mma16816(acc[mi][ni], ah[mi], b0, b1);
                        mma16816(acc[mi][ni], ah[mi], c0r, c1r);
                        mma16816(acc[mi][ni], al[mi], b0, b1);
                    }
                }
            }
        }
        buf = (buf + 1) % 3;
    }

    // ---- epilogue ----
    const int erow = lane >> 2;
    const int ecol = (lane & 3) << 1;

    if (!ROPE) {
#pragma unroll
        for (int mi = 0; mi < 4; mi++) {
#pragma unroll
            for (int ni = 0; ni < 4; ni++) {
                int r = block_row + wm * 64 + mi * 16 + erow;
                int col = block_col + wn * 32 + ni * 8 + ecol;
                float2 bv = *(const float2*)(bias + col);
                if (r < M) {
                    float2 o = make_float2(acc[mi][ni][0] + bv.x,
                                           acc[mi][ni][1] + bv.y);
                    *(float2*)(C + (size_t)r * N + col) = o;
                }
                if (r + 8 < M) {
                    float2 o = make_float2(acc[mi][ni][2] + bv.x,
                                           acc[mi][ni][3] + bv.y);
                    *(float2*)(C + (size_t)(r + 8) * N + col) = o;
                }
            }
        }
    } else {
        // fused RoPE + bf16 hi/lo split + scatter to Q/K/V
        const int sec = block_col / CDIM;               // 0=Q,1=K,2=V (const/CTA)
        const int hbase = (block_col % CDIM) / DHEAD;
        __nv_bfloat16* dh = sec == 0 ? gQh : (sec == 1 ? gKh : gVh);
        __nv_bfloat16* dl = sec == 0 ? gQl : (sec == 1 ? gKl : gVl);
#pragma unroll
        for (int mi = 0; mi < 4; mi++) {
#pragma unroll
            for (int rp = 0; rp < 2; rp++) {
                int r = block_row + wm * 64 + mi * 16 + erow + rp * 8;
                if (r >= M) continue;
                int bidx = r / NTOK;
                int n = r - bidx * NTOK;
#pragma unroll
                for (int ni = 0; ni < 4; ni++) {
                    int lc = wn * 32 + ni * 8 + ecol;
                    int col = block_col + lc;
                    float v0 = acc[mi][ni][rp * 2 + 0] + bias[col];
                    float v1 = acc[mi][ni][rp * 2 + 1] + bias[col + 1];
                    int d = lc & 63;
                    int h = hbase + (lc >> 6);
                    if (sec < 2 && n > 0) {
                        float cc = cosb[(size_t)(n - 1) * 32 + (d >> 1)];
                        float ss = sinb[(size_t)(n - 1) * 32 + (d >> 1)];
                        float t0 = v0 * cc - v1 * ss;
                        float t1 = v0 * ss + v1 * cc;
                        v0 = t0; v1 = t1;
                    }
                    float h0 = __bfloat162float(__float2bfloat16_rn(v0));
                    float h1 = __bfloat162float(__float2bfloat16_rn(v1));
                    size_t o = ((size_t)(bidx * HEADS + h) * NTOK + n) * DHEAD + d;
                    *(uint32_t*)(dh + o) = pack_bf16x2(h0, h1);
                    *(uint32_t*)(dl + o) = pack_bf16x2(v0 - h0, v1 - h1);
                }
            }
        }
    }
}

// ============== Flash attention on HMMA, bf16x3, 128 q-rows/CTA =============
// 2-stage cp.async double buffer for K/V. smem 96KB; 2 CTAs/SM.
#define ASM_QH   0
#define ASM_QL   16384
#define ASM_KV0  32768
#define ASM_KVSZ 32768                 // KH+0, KL+8192, VH+16384, VL+24576
#define ASM_TOTAL 98304

__global__ __launch_bounds__(256, 2) void k_attn_mma() {
    extern __shared__ __align__(128) char asmem[];
    const uint32_t sb = smem_to_u32(asmem);
    const int tid = threadIdx.x;
    const int lane = tid & 31;
    const int wid = tid >> 5;
    const int bh = blockIdx.y;
    const int q0 = blockIdx.x * 128;
    const size_t gbase = (size_t)bh * NTOK * DHEAD;

    // ---- load Q tile (persistent) ----
#pragma unroll
    for (int i = 0; i < 4; i++) {
        int u = tid + (i << 8);
        int r = u >> 3, c = u & 7;
        uint32_t so = (uint32_t)(r * 128 + ((c ^ (r & 7)) << 4));
        uint4 zh = make_uint4(0, 0, 0, 0), zl = zh;
        if (q0 + r < NTOK) {
            size_t g = gbase + (size_t)(q0 + r) * DHEAD + c * 8;
            zh = *(const uint4*)(gQh + g);
            zl = *(const uint4*)(gQl + g);
        }
        *(uint4*)(asmem + ASM_QH + so) = zh;
        *(uint4*)(asmem + ASM_QL + so) = zl;
    }

    // ---- K/V async stage loader ----
    auto issueKV = [&](int kt) {
        const int k0 = kt * 64;
        const uint32_t base = sb + ASM_KV0 + (uint32_t)(kt & 1) * ASM_KVSZ;
#pragma unroll
        for (int i = 0; i < 2; i++) {
            int u = tid + (i << 8);
            int r = u >> 3, c = u & 7;
            uint32_t so = (uint32_t)(r * 128 + ((c ^ (r & 7)) << 4));
            bool ok = (k0 + r) < NTOK;
            int rr = ok ? (k0 + r) : (NTOK - 1);
            size_t g = gbase + (size_t)rr * DHEAD + c * 8;
            cp_async16(base + so,         gKh + g, ok);
            cp_async16(base + 8192 + so,  gKl + g, ok);
            cp_async16(base + 16384 + so, gVh + g, ok);
            cp_async16(base + 24576 + so, gVl + g, ok);
        }
    };

    const int m0 = wid * 16;
    const int alr = m0 + (lane & 15);
    const int akc = lane >> 4;
    uint32_t offQ[4];
#pragma unroll
    for (int k16 = 0; k16 < 4; k16++)
        offQ[k16] = (uint32_t)(alr * 128 + (((2 * k16 + akc) ^ (alr & 7)) << 4));

    float m_[2] = {-1e30f, -1e30f};
    float l_[2] = {0.f, 0.f};
    float o[8][4];
#pragma unroll
    for (int t = 0; t < 8; t++)
#pragma unroll
        for (int j = 0; j < 4; j++) o[t][j] = 0.f;

    const float scale = 0.125f;

    issueKV(0); cp_commit();

    for (int kt = 0; kt < 10; kt++) {
        const int k0 = kt * 64;
        cp_wait<0>();          // stage kt landed
        __syncthreads();       // visible + all warps done with stage kt-1 buffer

        if (kt + 1 < 10) {     // prefetch overlaps compute of stage kt
            issueKV(kt + 1);
            cp_commit();
        }

        const uint32_t kvb = sb + ASM_KV0 + (uint32_t)(kt & 1) * ASM_KVSZ;

        // ---- S = Q @ K^T (x3 split) ----
        float s[8][4];
#pragma unroll
        for (int t = 0; t < 8; t++)
#pragma unroll
            for (int j = 0; j < 4; j++) s[t][j] = 0.f;

#pragma unroll
        for (int k16 = 0; k16 < 4; k16++) {
            uint32_t qh[4], ql[4];
            ldsm4(qh, sb + ASM_QH + offQ[k16]);
            ldsm4(ql, sb + ASM_QL + offQ[k16]);
#pragma unroll
            for (int nb = 0; nb < 4; nb++) {
                int krow = nb * 16 + (lane & 15);
                uint32_t off = (uint32_t)(krow * 128 +
                                (((2 * k16 + akc) ^ (krow & 7)) << 4));
                uint32_t kh[4], kl[4];
                ldsm4(kh, kvb + off);
                ldsm4(kl, kvb + 8192 + off);
#pragma unroll
                for (int nsub = 0; nsub < 2; nsub++) {
                    int t = nb * 2 + nsub;
                    uint32_t bh0 = kh[nsub], bh1 = kh[nsub + 2];
                    uint32_t bl0 = kl[nsub], bl1 = kl[nsub + 2];
                    mma16816(s[t], qh, bh0, bh1);
                    mma16816(s[t], qh, bl0, bl1);
                    mma16816(s[t], ql, bh0, bh1);
                }
            }
        }

        const bool lastt = (k0 + 64 > NTOK);
        float fi[2];
#pragma unroll
        for (int j = 0; j < 2; j++) {
            float rm = -1e30f;
#pragma unroll
            for (int t = 0; t < 8; t++) {
#pragma unroll
                for (int c = 0; c < 2; c++) {
                    float v = s[t][j * 2 + c] * scale;
                    if (lastt) {
                        int col = k0 + t * 8 + ((lane & 3) << 1) + c;
                        if (col >= NTOK) v = -1e30f;
                    }
                    s[t][j * 2 + c] = v;
                    rm = fmaxf(rm, v);
                }
            }
            rm = fmaxf(rm, __shfl_xor_sync(0xffffffffu, rm, 1));
            rm = fmaxf(rm, __shfl_xor_sync(0xffffffffu, rm, 2));
            float mn = fmaxf(m_[j], rm);
            fi[j] = __expf(m_[j] - mn);
            m_[j] = mn;
            float rs = 0.f;
#pragma unroll
            for (int t = 0; t < 8; t++) {
#pragma unroll
                for (int c = 0; c < 2; c++) {
                    float p = __expf(s[t][j * 2 + c] - mn);
                    s[t][j * 2 + c] = p;
                    rs += p;
                }
            }
            rs += __shfl_xor_sync(0xffffffffu, rs, 1);
            rs += __shfl_xor_sync(0xffffffffu, rs, 2);
            l_[j] = l_[j] * fi[j] + rs;
        }
#pragma unroll
        for (int t = 0; t < 8; t++) {
            o[t][0] *= fi[0]; o[t][1] *= fi[0];
            o[t][2] *= fi[1]; o[t][3] *= fi[1];
        }

        // ---- O += P @ V (x3 split) ----
#pragma unroll
        for (int t2 = 0; t2 < 4; t2++) {
            uint32_t ph[4], pl[4];
#pragma unroll
            for (int idx = 0; idx < 4; idx++) {
                int t = 2 * t2 + (idx >> 1);
                int j = idx & 1;
                float x0 = s[t][j * 2 + 0];
                float x1 = s[t][j * 2 + 1];
                float h0 = __bfloat162float(__float2bfloat16_rn(x0));
                float h1 = __bfloat162float(__float2bfloat16_rn(x1));
                ph[idx] = pack_bf16x2(h0, h1);
                pl[idx] = pack_bf16x2(x0 - h0, x1 - h1);
            }
            const int vm = lane >> 3;
            const int vk = t2 * 16 + ((vm & 1) << 3) + (lane & 7);
#pragma unroll
            for (int nb = 0; nb < 4; nb++) {
                int vc = nb * 2 + (vm >> 1);
                uint32_t off = (uint32_t)(vk * 128 + ((vc ^ (vk & 7)) << 4));
                uint32_t vh[4], vl[4];
                ldsm4t(vh, kvb + 16384 + off);
                ldsm4t(vl, kvb + 24576 + off);
                mma16816(o[nb * 2 + 0], ph, vh[0], vh[1]);
                mma16816(o[nb * 2 + 0], ph, vl[0], vl[1]);
                mma16816(o[nb * 2 + 0], pl, vh[0], vh[1]);
                mma16816(o[nb * 2 + 1], ph, vh[2], vh[3]);
                mma16816(o[nb * 2 + 1], ph, vl[2], vl[3]);
                mma16816(o[nb * 2 + 1], pl, vh[2], vh[3]);
            }
        }
    }

    const int b = bh / HEADS;
    const int h = bh % HEADS;
#pragma unroll
    for (int j = 0; j < 2; j++) {
        int n = q0 + m0 + (lane >> 2) + j * 8;
        if (n < NTOK) {
            float inv = 1.f / l_[j];
            size_t gr = (size_t)(b * NTOK + n) * CDIM + h * DHEAD;
#pragma unroll
            for (int t = 0; t < 8; t++) {
                int col = t * 8 + ((lane & 3) << 1);
                float x0 = o[t][j * 2 + 0] * inv;
                float x1 = o[t][j * 2 + 1] * inv;
                float h0 = __bfloat162float(__float2bfloat16_rn(x0));
                float h1 = __bfloat162float(__float2bfloat16_rn(x1));
                *(uint32_t*)(gCh + gr + col) = pack_bf16x2(h0, h1);
                *(uint32_t*)(gCl + gr + col) = pack_bf16x2(x0 - h0, x1 - h1);
            }
        }
    }
}

// ================================ launch ====================================
extern "C" void kernel_launch(void* const* d_in, const int* in_sizes, int n_in,
                              void* d_out, int out_size) {
    const float* x      = (const float*)d_in[0];
    const float* cosb   = (const float*)d_in[1];
    const float* sinb   = (const float*)d_in[2];
    const float* w_qkv  = (const float*)d_in[3];
    const float* b_qkv  = (const float*)d_in[4];
    const float* w_proj = (const float*)d_in[5];
    const float* b_proj = (const float*)d_in[6];
    float* out = (float*)d_out;

    cudaFuncSetAttribute(k_gemm_mma<true>,
                         cudaFuncAttributeMaxDynamicSharedMemorySize, GT_SMEM);
    cudaFuncSetAttribute(k_gemm_mma<false>,
                         cudaFuncAttributeMaxDynamicSharedMemorySize, GT_SMEM);
    cudaFuncSetAttribute(k_attn_mma,
                         cudaFuncAttributeMaxDynamicSharedMemorySize, ASM_TOTAL);

    __nv_bfloat16 *pAh, *pAl, *pCh, *pCl, *pWqh, *pWql, *pWph, *pWpl;
    cudaGetSymbolAddress((void**)&pAh,  gAh);
    cudaGetSymbolAddress((void**)&pAl,  gAl);
    cudaGetSymbolAddress((void**)&pCh,  gCh);
    cudaGetSymbolAddress((void**)&pCl,  gCl);
    cudaGetSymbolAddress((void**)&pWqh, gWqh);
    cudaGetSymbolAddress((void**)&pWql, gWql);
    cudaGetSymbolAddress((void**)&pWph, gWph);
    cudaGetSymbolAddress((void**)&pWpl, gWpl);

    // 0) fused operand preparation
    k_prep<<<NB_X + NB_WQ + NB_WP, 256>>>(x, w_qkv, w_proj);

    // 1) QKV GEMM + fused RoPE/split (HMMA bf16x3, cp.async pipeline)
    {
        dim3 grid(QKVCOLS / 128, (MROWS + 127) / 128);
        k_gemm_mma<true><<<grid, 256, GT_SMEM>>>(pAh, pAl, pWqh, pWql, b_qkv,
                                                 nullptr, MROWS, QKVCOLS,
                                                 cosb, sinb);
    }
    // 2) attention (HMMA bf16x3, double-buffered K/V) — writes gCh/gCl
    {
        dim3 grid((NTOK + 127) / 128, BHTOT);
        k_attn_mma<<<grid, 256, ASM_TOTAL>>>();
    }
    // 3) output projection (HMMA bf16x3, cp.async pipeline)
    {
        dim3 grid(CDIM / 128, (MROWS + 127) / 128);
        k_gemm_mma<false><<<grid, 256, GT_SMEM>>>(pCh, pCl, pWph, pWpl, b_proj,
                                                  out, MROWS, CDIM,
                                                  nullptr, nullptr);
    }
}